// round 8
// baseline (speedup 1.0000x reference)
#include <cuda_runtime.h>
#include <math.h>

// ---------------- scratch (device globals; no allocations) ----------------
#define NB 16
__device__ float g_h1[NB*64*256*256];
__device__ float g_h2[NB*128*128*128];
__device__ float g_h3[NB*256*64*64];
__device__ float g_z [NB*512*32*32];
__device__ float g_zq[NB*512*32*32];
__device__ float g_g1[NB*256*64*64];
__device__ float g_g2[NB*128*128*128];
__device__ float g_g3[NB*64*256*256];
__device__ float g_cn[8192];
__device__ int   g_idx[16384];

// ---------------- 3x3 conv, pad=1, 8-wide, TC output channels ----------------
// Thread: 8 horizontal outputs x TC output channels. Coalesced float4 loads,
// halo via shfl. Weights smem [ci][oc][ky][4] -> one LDS.128 per (oc,row).
// ACT: 0 none, 1 relu, 2 sigmoid
template<int STRIDE, int TC, int ACT>
__global__ void __launch_bounds__(128) conv8s_k(
    const float* __restrict__ in, const float* __restrict__ wgt,
    const float* __restrict__ bias, float* __restrict__ out,
    int Cin, int Cout, int Hin, int Win, int Hout, int Wout)
{
    constexpr int CICH = 64;
    constexpr int NW = (STRIDE == 1) ? 10 : 17;
    __shared__ float wsf[CICH * TC * 12];

    const int tid  = threadIdx.x;
    const int W8   = Wout >> 3;
    const int rows = 128 / W8;
    const int q    = tid % W8;
    const int oy   = blockIdx.y * rows + tid / W8;
    const int ox0  = q * 8;
    const int ocg  = blockIdx.x * TC;
    const int n    = blockIdx.z;

    float acc[TC][8];
#pragma unroll
    for (int o = 0; o < TC; o++)
#pragma unroll
        for (int j = 0; j < 8; j++) acc[o][j] = 0.f;

    bool rval[3]; int iyo[3];
#pragma unroll
    for (int ky = 0; ky < 3; ky++) {
        int iy = oy * STRIDE + ky - 1;
        rval[ky] = (iy >= 0 && iy < Hin);
        iyo[ky] = iy < 0 ? 0 : (iy >= Hin ? Hin - 1 : iy);
    }

    auto loadRow = [&](float (&w)[NW], int cabs, int ky) {
        const float* rp = in + ((size_t)(n * Cin + cabs) * Hin + iyo[ky]) * Win;
        if (STRIDE == 1) {
            float4 a = *(const float4*)(rp + ox0);
            float4 b = *(const float4*)(rp + ox0 + 4);
            float lft = __shfl_up_sync(0xffffffffu, b.w, 1);
            float rgt = __shfl_down_sync(0xffffffffu, a.x, 1);
            if (q == 0) lft = 0.f;
            if (q == W8 - 1) rgt = 0.f;
            w[0]=lft; w[1]=a.x; w[2]=a.y; w[3]=a.z; w[4]=a.w;
            w[5]=b.x; w[6]=b.y; w[7]=b.z; w[8]=b.w; w[9]=rgt;
        } else {
            const int ib = ox0 * 2;
            float4 a = *(const float4*)(rp + ib);
            float4 b = *(const float4*)(rp + ib + 4);
            float4 c = *(const float4*)(rp + ib + 8);
            float4 d = *(const float4*)(rp + ib + 12);
            float lft = __shfl_up_sync(0xffffffffu, d.w, 1);
            if (q == 0) lft = 0.f;
            w[0]=lft;
            w[1]=a.x; w[2]=a.y; w[3]=a.z; w[4]=a.w;
            w[5]=b.x; w[6]=b.y; w[7]=b.z; w[8]=b.w;
            w[9]=c.x; w[10]=c.y; w[11]=c.z; w[12]=c.w;
            w[13]=d.x; w[14]=d.y; w[15]=d.z; w[16]=d.w;
        }
        if (!rval[ky]) {
#pragma unroll
            for (int i = 0; i < NW; i++) w[i] = 0.f;
        }
    };

    auto computeRow = [&](float (&w)[NW], int ci, int ky) {
#pragma unroll
        for (int oc = 0; oc < TC; oc++) {
            const float4 wv = *(const float4*)(wsf + (ci * TC + oc) * 12 + ky * 4);
#pragma unroll
            for (int j = 0; j < 8; j++) {
                float a = acc[oc][j];
                a = fmaf(w[j * STRIDE + 0], wv.x, a);
                a = fmaf(w[j * STRIDE + 1], wv.y, a);
                a = fmaf(w[j * STRIDE + 2], wv.z, a);
                acc[oc][j] = a;
            }
        }
    };

    float bufA[NW], bufB[NW];
    for (int cc = 0; cc < Cin; cc += CICH) {
        const int chunk = min(CICH, Cin - cc);
        __syncthreads();
        for (int i = tid; i < chunk * TC * 9; i += 128) {
            int ci = i / (TC * 9);
            int r  = i - ci * (TC * 9);
            int oc = r / 9;
            int k  = r - oc * 9;
            wsf[(ci * TC + oc) * 12 + (k / 3) * 4 + (k % 3)] =
                wgt[(size_t)(ocg + oc) * Cin * 9 + (size_t)(cc + ci) * 9 + k];
        }
        __syncthreads();
        const int total = chunk * 3;
        loadRow(bufA, cc, 0);
        for (int m = 0; m < total; m++) {
            const int mn = m + 1;
            if (m & 1) {
                if (mn < total) loadRow(bufA, cc + mn / 3, mn % 3);
                computeRow(bufB, m / 3, m % 3);
            } else {
                if (mn < total) loadRow(bufB, cc + mn / 3, mn % 3);
                computeRow(bufA, m / 3, m % 3);
            }
        }
    }

#pragma unroll
    for (int oc = 0; oc < TC; oc++) {
        float bv = bias[ocg + oc];
        float* op = out + (((size_t)n * Cout + ocg + oc) * Hout + oy) * Wout + ox0;
        float v[8];
#pragma unroll
        for (int j = 0; j < 8; j++) {
            float a = acc[oc][j] + bv;
            if (ACT == 1) a = a > 0.f ? a : 0.f;
            if (ACT == 2) a = 1.f / (1.f + expf(-a));
            v[j] = a;
        }
        *(float4*)(op)     = make_float4(v[0], v[1], v[2], v[3]);
        *(float4*)(op + 4) = make_float4(v[4], v[5], v[6], v[7]);
    }
}

// ---------------- transposed conv k=3 s=2 p=1 op=1, scalar, TC=8 --------------
// R6-proven: thread = 2x4 output block for 8 ocs; weights [ci][oc][12].
template<int ACT>
__global__ void __launch_bounds__(128) deconvS_k(
    const float* __restrict__ in, const float* __restrict__ wgt,  // [Cin][Cout][3][3]
    const float* __restrict__ bias, float* __restrict__ out,
    int Cin, int Cout, int Hin, int Win)
{
    constexpr int CICH = 32;
    constexpr int TC = 8;
    __shared__ float wsf[CICH * TC * 12];

    const int Hout = Hin * 2, Wout = Win * 2;
    const int tid  = threadIdx.x;
    const int W4   = Wout >> 2;
    const int rows = 128 / W4;
    const int q    = tid % W4;
    const int a    = blockIdx.y * rows + tid / W4;
    const int b    = q * 2;
    const int ocg  = blockIdx.x * TC;
    const int n    = blockIdx.z;

    const bool v_a1 = (a + 1) < Hin;
    const bool v_b2 = (b + 2) < Win;

    float acc[TC][8];
#pragma unroll
    for (int o = 0; o < TC; o++)
#pragma unroll
        for (int j = 0; j < 8; j++) acc[o][j] = 0.f;

    auto loadRaw = [&](float (&rw)[6], int cabs) {
        const float* ip = in + ((size_t)n * Cin + cabs) * Hin * Win;
        const float* r0 = ip + (size_t)a * Win + b;
        float2 p0 = *(const float2*)r0;
        rw[0] = p0.x; rw[1] = p0.y;
        rw[2] = v_b2 ? r0[2] : 0.f;
        if (v_a1) {
            const float* r1 = r0 + Win;
            float2 p1 = *(const float2*)r1;
            rw[3] = p1.x; rw[4] = p1.y; rw[5] = v_b2 ? r1[2] : 0.f;
        } else {
            rw[3] = 0.f; rw[4] = 0.f; rw[5] = 0.f;
        }
    };
    auto computeCi = [&](float (&rw)[6], int ci) {
        float i00 = rw[0], i01 = rw[1], i02 = rw[2];
        float i10 = rw[3], i11 = rw[4], i12 = rw[5];
#pragma unroll
        for (int oc = 0; oc < TC; oc++) {
            const float* wp = wsf + (ci * TC + oc) * 12;
            const float4 A = *(const float4*)(wp);
            const float4 B = *(const float4*)(wp + 4);
            const float w22 = wp[8];
            float w00=A.x, w01=A.y, w02=A.z, w10=A.w;
            float w11=B.x, w12=B.y, w20=B.z, w21=B.w;
            acc[oc][0] = fmaf(i00, w11, acc[oc][0]);
            acc[oc][1] = fmaf(i00, w12, fmaf(i01, w10, acc[oc][1]));
            acc[oc][2] = fmaf(i01, w11, acc[oc][2]);
            acc[oc][3] = fmaf(i01, w12, fmaf(i02, w10, acc[oc][3]));
            acc[oc][4] = fmaf(i00, w21, fmaf(i10, w01, acc[oc][4]));
            acc[oc][5] = fmaf(i00, w22, fmaf(i01, w20, fmaf(i10, w02, fmaf(i11, w00, acc[oc][5]))));
            acc[oc][6] = fmaf(i01, w21, fmaf(i11, w01, acc[oc][6]));
            acc[oc][7] = fmaf(i01, w22, fmaf(i02, w20, fmaf(i11, w02, fmaf(i12, w00, acc[oc][7]))));
        }
    };

    float rawA[6], rawB[6];
    for (int cc = 0; cc < Cin; cc += CICH) {
        const int chunk = min(CICH, Cin - cc);
        __syncthreads();
        for (int i = tid; i < chunk * TC * 9; i += 128) {
            int ci = i / (TC * 9);
            int r  = i - ci * (TC * 9);
            int oc = r / 9;
            int k  = r - oc * 9;
            wsf[(ci * TC + oc) * 12 + k] =
                wgt[(size_t)(cc + ci) * Cout * 9 + (size_t)(ocg + oc) * 9 + k];
        }
        __syncthreads();
        loadRaw(rawA, cc);
        for (int ci = 0; ci < chunk; ci += 2) {
            if (ci + 1 < chunk) loadRaw(rawB, cc + ci + 1);
            computeCi(rawA, ci);
            if (ci + 2 < chunk) loadRaw(rawA, cc + ci + 2);
            if (ci + 1 < chunk) computeCi(rawB, ci + 1);
        }
    }

#pragma unroll
    for (int oc = 0; oc < TC; oc++) {
        float bv = bias[ocg + oc];
        float* op = out + (((size_t)n * Cout + ocg + oc) * Hout + 2 * a) * Wout + 4 * q;
        float v0[4], v1[4];
#pragma unroll
        for (int j = 0; j < 4; j++) {
            float x0 = acc[oc][j] + bv;
            float x1 = acc[oc][4 + j] + bv;
            if (ACT == 1) { x0 = x0 > 0.f ? x0 : 0.f; x1 = x1 > 0.f ? x1 : 0.f; }
            v0[j] = x0; v1[j] = x1;
        }
        *(float4*)(op)        = make_float4(v0[0], v0[1], v0[2], v0[3]);
        *(float4*)(op + Wout) = make_float4(v1[0], v1[1], v1[2], v1[3]);
    }
}

// ---------------- codebook row norms ----------------
__global__ void __launch_bounds__(256) cnorm_k(const float* __restrict__ cb,
                                               float* __restrict__ cn)
{
    const int warp = threadIdx.x >> 5, lane = threadIdx.x & 31;
    const int code = blockIdx.x * 8 + warp;
    const float* p = cb + (size_t)code * 512;
    float s = 0.f;
    for (int d = lane; d < 512; d += 32) { float v = p[d]; s = fmaf(v, v, s); }
#pragma unroll
    for (int o = 16; o > 0; o >>= 1) s += __shfl_xor_sync(0xffffffffu, s, o);
    if (lane == 0) cn[code] = s;
}

// ---------------- quantizer: 32 rows/block, thread = 8 rows x 8 codes ---------
// Reads z directly from NCHW (block = one (b,y) row of 32 pixels). smem:
// zs [32][520] channels-last rows (66.6KB), cbt double-buffered [2][1024][20] (160KB)
#define ZPQ 520
#define CPQ 20
__global__ void __launch_bounds__(512) quant8_k(const float* __restrict__ z,
                                                const float* __restrict__ cb,
                                                const float* __restrict__ cn,
                                                int* __restrict__ idx)
{
    extern __shared__ float sm[];
    float* zs  = sm;                 // 32*520
    float* cbt = sm + 32 * ZPQ;      // 2 * 1024*20
    const int tid = threadIdx.x;
    const int t   = tid & 127;
    const int rg  = tid >> 7;
    const int r0  = blockIdx.x * 32;
    const int bb  = r0 >> 10;        // batch
    const int y   = (r0 >> 5) & 31;  // row

    // stage z: zs[x][d] = z[bb][d][y][x]  (coalesced 128B reads over x)
    for (int i = tid; i < 512 * 32; i += 512) {
        int d = i >> 5, x = i & 31;
        zs[x * ZPQ + d] = z[(((size_t)bb * 512 + d) * 32 + y) * 32 + x];
    }

    float best[8]; int bi[8];
#pragma unroll
    for (int r = 0; r < 8; r++) { best[r] = 3.4e38f; bi[r] = 0; }

    auto stage = [&](int cbase, int dch, int buf) {
        float* dst = cbt + buf * (1024 * CPQ);
        for (int i = tid; i < 4096; i += 512) {
            int c = i >> 2, dq = i & 3;
            float4 v = *(const float4*)(cb + (size_t)(cbase + c) * 512 + dch * 16 + dq * 4);
            *(float4*)(dst + c * CPQ + dq * 4) = v;
        }
    };

    for (int ct = 0; ct < 8; ct++) {
        const int cbase = ct * 1024;
        float acc[8][8];
#pragma unroll
        for (int rr = 0; rr < 8; rr++)
#pragma unroll
            for (int k = 0; k < 8; k++) acc[rr][k] = 0.f;

        __syncthreads();
        stage(cbase, 0, 0);
        for (int dch = 0; dch < 32; dch++) {
            __syncthreads();
            if (dch + 1 < 32) stage(cbase, dch + 1, (dch + 1) & 1);
            const float* cbuf = cbt + (dch & 1) * (1024 * CPQ);
#pragma unroll
            for (int dq = 0; dq < 4; dq++) {
                float4 zv[8];
#pragma unroll
                for (int rr = 0; rr < 8; rr++)
                    zv[rr] = *(const float4*)(zs + (rg * 8 + rr) * ZPQ + dch * 16 + dq * 4);
#pragma unroll
                for (int k = 0; k < 8; k++) {
                    float4 cv = *(const float4*)(cbuf + (k * 128 + t) * CPQ + dq * 4);
#pragma unroll
                    for (int rr = 0; rr < 8; rr++) {
                        float a = acc[rr][k];
                        a = fmaf(zv[rr].x, cv.x, a);
                        a = fmaf(zv[rr].y, cv.y, a);
                        a = fmaf(zv[rr].z, cv.z, a);
                        a = fmaf(zv[rr].w, cv.w, a);
                        acc[rr][k] = a;
                    }
                }
            }
        }
#pragma unroll
        for (int k = 0; k < 8; k++) {
            int cand = cbase + k * 128 + t;
            float nv = cn[cand];
#pragma unroll
            for (int rr = 0; rr < 8; rr++) {
                float s = nv - 2.f * acc[rr][k];
                if (s < best[rr]) { best[rr] = s; bi[rr] = cand; }
            }
        }
    }

    float* sv = sm;
    int*   si = (int*)(sm + 512);
    for (int rr = 0; rr < 8; rr++) {
        __syncthreads();
        sv[tid] = best[rr]; si[tid] = bi[rr];
        __syncthreads();
        for (int s = 64; s > 0; s >>= 1) {
            if (t < s) {
                float ov = sv[tid + s]; int oi = si[tid + s];
                if (ov < sv[tid] || (ov == sv[tid] && oi < si[tid])) { sv[tid] = ov; si[tid] = oi; }
            }
            __syncthreads();
        }
        if (t == 0) idx[r0 + rg * 8 + rr] = si[tid];
    }
}

// ---------------- zq gather ----------------
__global__ void __launch_bounds__(256) zqg_k(const float* __restrict__ cb,
                                             const int* __restrict__ idx,
                                             float* __restrict__ zq)
{
    size_t i = (size_t)blockIdx.x * 256 + threadIdx.x;
    if (i >= (size_t)NB * 512 * 32 * 32) return;
    int x = (int)(i & 31);
    int y = (int)((i >> 5) & 31);
    int c = (int)((i >> 10) & 511);
    int bb = (int)(i >> 19);
    int n = bb * 1024 + y * 32 + x;
    zq[i] = cb[(size_t)idx[n] * 512 + c];
}

// ---------------- indices -> tail of output ----------------
__global__ void __launch_bounds__(256) idxout_k(const int* __restrict__ idx,
                                                float* __restrict__ out,
                                                long out_off, long out_size)
{
    int i = blockIdx.x * 256 + threadIdx.x;
    if (i < 16384 && out_off + i < out_size) out[out_off + i] = (float)idx[i];
}

// ---------------- host launcher ----------------
extern "C" void kernel_launch(void* const* d_in, const int* in_sizes, int n_in,
                              void* d_out, int out_size)
{
    const float* x  = (const float*)d_in[0];
    const float* w1 = (const float*)d_in[1];  const float* b1 = (const float*)d_in[2];
    const float* w2 = (const float*)d_in[3];  const float* b2 = (const float*)d_in[4];
    const float* w3 = (const float*)d_in[5];  const float* b3 = (const float*)d_in[6];
    const float* w4 = (const float*)d_in[7];  const float* b4 = (const float*)d_in[8];
    const float* cb = (const float*)d_in[9];
    const float* d1w = (const float*)d_in[10]; const float* d1b = (const float*)d_in[11];
    const float* d2w = (const float*)d_in[12]; const float* d2b = (const float*)d_in[13];
    const float* d3w = (const float*)d_in[14]; const float* d3b = (const float*)d_in[15];
    const float* wo = (const float*)d_in[16]; const float* bo = (const float*)d_in[17];
    float* out = (float*)d_out;

    float *h1, *h2, *h3, *z, *zq, *g1, *g2, *g3, *cn;
    int* idx;
    cudaGetSymbolAddress((void**)&h1, g_h1);
    cudaGetSymbolAddress((void**)&h2, g_h2);
    cudaGetSymbolAddress((void**)&h3, g_h3);
    cudaGetSymbolAddress((void**)&z,  g_z);
    cudaGetSymbolAddress((void**)&zq, g_zq);
    cudaGetSymbolAddress((void**)&g1, g_g1);
    cudaGetSymbolAddress((void**)&g2, g_g2);
    cudaGetSymbolAddress((void**)&g3, g_g3);
    cudaGetSymbolAddress((void**)&cn, g_cn);
    cudaGetSymbolAddress((void**)&idx, g_idx);

    // codebook norms first (independent)
    cnorm_k<<<1024, 256>>>(cb, cn);

    // Encoder
    conv8s_k<1, 8, 1><<<dim3( 8, 64, NB), 128>>>(x,  w1, b1, h1,   3,  64, 256, 256, 256, 256);
    conv8s_k<2, 8, 1><<<dim3(16, 16, NB), 128>>>(h1, w2, b2, h2,  64, 128, 256, 256, 128, 128);
    conv8s_k<2, 8, 1><<<dim3(32,  4, NB), 128>>>(h2, w3, b3, h3, 128, 256, 128, 128,  64,  64);
    conv8s_k<2, 8, 0><<<dim3(64,  1, NB), 128>>>(h3, w4, b4, z,  256, 512,  64,  64,  32,  32);

    // Quantize (z read directly; no transpose kernel)
    const int qsmem = (32 * ZPQ + 2 * 1024 * CPQ) * 4;  // 230400 B
    cudaFuncSetAttribute(quant8_k, cudaFuncAttributeMaxDynamicSharedMemorySize, qsmem);
    quant8_k<<<512, 512, qsmem>>>(z, cb, cn, idx);
    zqg_k<<<(NB * 512 * 32 * 32 + 255) / 256, 256>>>(cb, idx, zq);

    // Decoder (R6-proven deconvS, TC=8)
    deconvS_k<1><<<dim3(32,  4, NB), 128>>>(zq, d1w, d1b, g1, 512, 256,  32,  32);
    deconvS_k<1><<<dim3(16, 16, NB), 128>>>(g1, d2w, d2b, g2, 256, 128,  64,  64);
    deconvS_k<1><<<dim3( 8, 64, NB), 128>>>(g2, d3w, d3b, g3, 128,  64, 128, 128);
    // Final sigmoid conv: 8-wide, TC=3
    conv8s_k<1, 3, 2><<<dim3(1, 64, NB), 128>>>(g3, wo, bo, out, 64, 3, 256, 256, 256, 256);

    // Indices appended after reconstruction
    idxout_k<<<64, 256>>>(idx, out, (long)NB * 3 * 256 * 256, (long)out_size);
}

// round 9
// speedup vs baseline: 1.0008x; 1.0008x over previous
#include <cuda_runtime.h>
#include <math.h>

// ---------------- scratch (device globals; no allocations) ----------------
#define NB 16
__device__ float g_h1[NB*64*256*256];
__device__ float g_h2[NB*128*128*128];
__device__ float g_h3[NB*256*64*64];
__device__ float g_z [NB*512*32*32];
__device__ float g_zf[NB*1024*512];
__device__ float g_zq[NB*512*32*32];
__device__ float g_g1[NB*256*64*64];
__device__ float g_g2[NB*128*128*128];
__device__ float g_g3[NB*64*256*256];
__device__ float g_cn[8192];
__device__ int   g_idx[16384];

// ---------------- 3x3 conv, pad=1, 8-wide, TC output channels ----------------
// Thread: 8 horizontal outputs x TC output channels. Coalesced float4 loads,
// halo via shfl. Weights smem [ci][oc][ky][4] -> one LDS.128 per (oc,row).
// ACT: 0 none, 1 relu, 2 sigmoid
template<int STRIDE, int TC, int ACT>
__global__ void __launch_bounds__(128) conv8s_k(
    const float* __restrict__ in, const float* __restrict__ wgt,
    const float* __restrict__ bias, float* __restrict__ out,
    int Cin, int Cout, int Hin, int Win, int Hout, int Wout)
{
    constexpr int CICH = 32;
    constexpr int NW = (STRIDE == 1) ? 10 : 17;
    __shared__ float wsf[CICH * TC * 12];

    const int tid  = threadIdx.x;
    const int W8   = Wout >> 3;
    const int rows = 128 / W8;
    const int q    = tid % W8;
    const int oy   = blockIdx.y * rows + tid / W8;
    const int ox0  = q * 8;
    const int ocg  = blockIdx.x * TC;
    const int n    = blockIdx.z;

    float acc[TC][8];
#pragma unroll
    for (int o = 0; o < TC; o++)
#pragma unroll
        for (int j = 0; j < 8; j++) acc[o][j] = 0.f;

    bool rval[3]; int iyo[3];
#pragma unroll
    for (int ky = 0; ky < 3; ky++) {
        int iy = oy * STRIDE + ky - 1;
        rval[ky] = (iy >= 0 && iy < Hin);
        iyo[ky] = iy < 0 ? 0 : (iy >= Hin ? Hin - 1 : iy);
    }

    auto loadRow = [&](float (&w)[NW], int cabs, int ky) {
        const float* rp = in + ((size_t)(n * Cin + cabs) * Hin + iyo[ky]) * Win;
        if (STRIDE == 1) {
            float4 a = *(const float4*)(rp + ox0);
            float4 b = *(const float4*)(rp + ox0 + 4);
            float lft = __shfl_up_sync(0xffffffffu, b.w, 1);
            float rgt = __shfl_down_sync(0xffffffffu, a.x, 1);
            if (q == 0) lft = 0.f;
            if (q == W8 - 1) rgt = 0.f;
            w[0]=lft; w[1]=a.x; w[2]=a.y; w[3]=a.z; w[4]=a.w;
            w[5]=b.x; w[6]=b.y; w[7]=b.z; w[8]=b.w; w[9]=rgt;
        } else {
            const int ib = ox0 * 2;
            float4 a = *(const float4*)(rp + ib);
            float4 b = *(const float4*)(rp + ib + 4);
            float4 c = *(const float4*)(rp + ib + 8);
            float4 d = *(const float4*)(rp + ib + 12);
            float lft = __shfl_up_sync(0xffffffffu, d.w, 1);
            if (q == 0) lft = 0.f;
            w[0]=lft;
            w[1]=a.x; w[2]=a.y; w[3]=a.z; w[4]=a.w;
            w[5]=b.x; w[6]=b.y; w[7]=b.z; w[8]=b.w;
            w[9]=c.x; w[10]=c.y; w[11]=c.z; w[12]=c.w;
            w[13]=d.x; w[14]=d.y; w[15]=d.z; w[16]=d.w;
        }
        if (!rval[ky]) {
#pragma unroll
            for (int i = 0; i < NW; i++) w[i] = 0.f;
        }
    };

    auto computeRow = [&](float (&w)[NW], int ci, int ky) {
#pragma unroll
        for (int oc = 0; oc < TC; oc++) {
            const float4 wv = *(const float4*)(wsf + (ci * TC + oc) * 12 + ky * 4);
#pragma unroll
            for (int j = 0; j < 8; j++) {
                float a = acc[oc][j];
                a = fmaf(w[j * STRIDE + 0], wv.x, a);
                a = fmaf(w[j * STRIDE + 1], wv.y, a);
                a = fmaf(w[j * STRIDE + 2], wv.z, a);
                acc[oc][j] = a;
            }
        }
    };

    float bufA[NW], bufB[NW];
    for (int cc = 0; cc < Cin; cc += CICH) {
        const int chunk = min(CICH, Cin - cc);
        __syncthreads();
        for (int i = tid; i < chunk * TC * 9; i += 128) {
            int ci = i / (TC * 9);
            int r  = i - ci * (TC * 9);
            int oc = r / 9;
            int k  = r - oc * 9;
            wsf[(ci * TC + oc) * 12 + (k / 3) * 4 + (k % 3)] =
                wgt[(size_t)(ocg + oc) * Cin * 9 + (size_t)(cc + ci) * 9 + k];
        }
        __syncthreads();
        const int total = chunk * 3;
        loadRow(bufA, cc, 0);
        for (int m = 0; m < total; m++) {
            const int mn = m + 1;
            if (m & 1) {
                if (mn < total) loadRow(bufA, cc + mn / 3, mn % 3);
                computeRow(bufB, m / 3, m % 3);
            } else {
                if (mn < total) loadRow(bufB, cc + mn / 3, mn % 3);
                computeRow(bufA, m / 3, m % 3);
            }
        }
    }

#pragma unroll
    for (int oc = 0; oc < TC; oc++) {
        float bv = bias[ocg + oc];
        float* op = out + (((size_t)n * Cout + ocg + oc) * Hout + oy) * Wout + ox0;
        float v[8];
#pragma unroll
        for (int j = 0; j < 8; j++) {
            float a = acc[oc][j] + bv;
            if (ACT == 1) a = a > 0.f ? a : 0.f;
            if (ACT == 2) a = 1.f / (1.f + expf(-a));
            v[j] = a;
        }
        *(float4*)(op)     = make_float4(v[0], v[1], v[2], v[3]);
        *(float4*)(op + 4) = make_float4(v[4], v[5], v[6], v[7]);
    }
}

// ---------------- transposed conv k=3 s=2 p=1 op=1, scalar, TC=8 --------------
template<int ACT>
__global__ void __launch_bounds__(128) deconvS_k(
    const float* __restrict__ in, const float* __restrict__ wgt,  // [Cin][Cout][3][3]
    const float* __restrict__ bias, float* __restrict__ out,
    int Cin, int Cout, int Hin, int Win)
{
    constexpr int CICH = 32;
    constexpr int TC = 8;
    __shared__ float wsf[CICH * TC * 12];

    const int Hout = Hin * 2, Wout = Win * 2;
    const int tid  = threadIdx.x;
    const int W4   = Wout >> 2;
    const int rows = 128 / W4;
    const int q    = tid % W4;
    const int a    = blockIdx.y * rows + tid / W4;
    const int b    = q * 2;
    const int ocg  = blockIdx.x * TC;
    const int n    = blockIdx.z;

    const bool v_a1 = (a + 1) < Hin;
    const bool v_b2 = (b + 2) < Win;

    float acc[TC][8];
#pragma unroll
    for (int o = 0; o < TC; o++)
#pragma unroll
        for (int j = 0; j < 8; j++) acc[o][j] = 0.f;

    auto loadRaw = [&](float (&rw)[6], int cabs) {
        const float* ip = in + ((size_t)n * Cin + cabs) * Hin * Win;
        const float* r0 = ip + (size_t)a * Win + b;
        float2 p0 = *(const float2*)r0;
        rw[0] = p0.x; rw[1] = p0.y;
        rw[2] = v_b2 ? r0[2] : 0.f;
        if (v_a1) {
            const float* r1 = r0 + Win;
            float2 p1 = *(const float2*)r1;
            rw[3] = p1.x; rw[4] = p1.y; rw[5] = v_b2 ? r1[2] : 0.f;
        } else {
            rw[3] = 0.f; rw[4] = 0.f; rw[5] = 0.f;
        }
    };
    auto computeCi = [&](float (&rw)[6], int ci) {
        float i00 = rw[0], i01 = rw[1], i02 = rw[2];
        float i10 = rw[3], i11 = rw[4], i12 = rw[5];
#pragma unroll
        for (int oc = 0; oc < TC; oc++) {
            const float* wp = wsf + (ci * TC + oc) * 12;
            const float4 A = *(const float4*)(wp);
            const float4 B = *(const float4*)(wp + 4);
            const float w22 = wp[8];
            float w00=A.x, w01=A.y, w02=A.z, w10=A.w;
            float w11=B.x, w12=B.y, w20=B.z, w21=B.w;
            acc[oc][0] = fmaf(i00, w11, acc[oc][0]);
            acc[oc][1] = fmaf(i00, w12, fmaf(i01, w10, acc[oc][1]));
            acc[oc][2] = fmaf(i01, w11, acc[oc][2]);
            acc[oc][3] = fmaf(i01, w12, fmaf(i02, w10, acc[oc][3]));
            acc[oc][4] = fmaf(i00, w21, fmaf(i10, w01, acc[oc][4]));
            acc[oc][5] = fmaf(i00, w22, fmaf(i01, w20, fmaf(i10, w02, fmaf(i11, w00, acc[oc][5]))));
            acc[oc][6] = fmaf(i01, w21, fmaf(i11, w01, acc[oc][6]));
            acc[oc][7] = fmaf(i01, w22, fmaf(i02, w20, fmaf(i11, w02, fmaf(i12, w00, acc[oc][7]))));
        }
    };

    float rawA[6], rawB[6];
    for (int cc = 0; cc < Cin; cc += CICH) {
        const int chunk = min(CICH, Cin - cc);
        __syncthreads();
        for (int i = tid; i < chunk * TC * 9; i += 128) {
            int ci = i / (TC * 9);
            int r  = i - ci * (TC * 9);
            int oc = r / 9;
            int k  = r - oc * 9;
            wsf[(ci * TC + oc) * 12 + k] =
                wgt[(size_t)(cc + ci) * Cout * 9 + (size_t)(ocg + oc) * 9 + k];
        }
        __syncthreads();
        loadRaw(rawA, cc);
        for (int ci = 0; ci < chunk; ci += 2) {
            if (ci + 1 < chunk) loadRaw(rawB, cc + ci + 1);
            computeCi(rawA, ci);
            if (ci + 2 < chunk) loadRaw(rawA, cc + ci + 2);
            if (ci + 1 < chunk) computeCi(rawB, ci + 1);
        }
    }

#pragma unroll
    for (int oc = 0; oc < TC; oc++) {
        float bv = bias[ocg + oc];
        float* op = out + (((size_t)n * Cout + ocg + oc) * Hout + 2 * a) * Wout + 4 * q;
        float v0[4], v1[4];
#pragma unroll
        for (int j = 0; j < 4; j++) {
            float x0 = acc[oc][j] + bv;
            float x1 = acc[oc][4 + j] + bv;
            if (ACT == 1) { x0 = x0 > 0.f ? x0 : 0.f; x1 = x1 > 0.f ? x1 : 0.f; }
            v0[j] = x0; v1[j] = x1;
        }
        *(float4*)(op)        = make_float4(v0[0], v0[1], v0[2], v0[3]);
        *(float4*)(op + Wout) = make_float4(v1[0], v1[1], v1[2], v1[3]);
    }
}

// ---------------- z [B,512,32,32] -> zf [16384, 512] ----------------
__global__ void __launch_bounds__(256) zt_k(const float* __restrict__ z,
                                            float* __restrict__ zf)
{
    __shared__ float t[128 * 33];
    const int blk = blockIdx.x;
    const int bb  = blk >> 5;
    const int y   = blk & 31;
    const int tid = threadIdx.x;
    for (int cc = 0; cc < 512; cc += 128) {
        __syncthreads();
        for (int i = tid; i < 128 * 32; i += 256) {
            int c = i >> 5, x = i & 31;
            t[c * 33 + x] = z[(((size_t)bb * 512 + cc + c) * 32 + y) * 32 + x];
        }
        __syncthreads();
        for (int i = tid; i < 32 * 128; i += 256) {
            int x = i >> 7, c = i & 127;
            zf[((size_t)bb * 1024 + y * 32 + x) * 512 + cc + c] = t[c * 33 + x];
        }
    }
}

// ---------------- codebook row norms ----------------
__global__ void __launch_bounds__(256) cnorm_k(const float* __restrict__ cb,
                                               float* __restrict__ cn)
{
    const int warp = threadIdx.x >> 5, lane = threadIdx.x & 31;
    const int code = blockIdx.x * 8 + warp;
    const float* p = cb + (size_t)code * 512;
    float s = 0.f;
    for (int d = lane; d < 512; d += 32) { float v = p[d]; s = fmaf(v, v, s); }
#pragma unroll
    for (int o = 16; o > 0; o >>= 1) s += __shfl_xor_sync(0xffffffffu, s, o);
    if (lane == 0) cn[code] = s;
}

// ---------------- quantizer: 16 rows/block, thread = 4 rows x 8 codes ---------
// 1024 blocks -> 6.92 waves (98.9% wave efficiency vs 86.5% at 512 blocks).
// smem: zs [16][520] (33.3KB), cbt double-buffered [2][1024][20] (160KB)
#define ZPQ 520
#define CPQ 20
__global__ void __launch_bounds__(512) quant16_k(const float* __restrict__ zf,
                                                 const float* __restrict__ cb,
                                                 const float* __restrict__ cn,
                                                 int* __restrict__ idx)
{
    extern __shared__ float sm[];
    float* zs  = sm;                 // 16*520
    float* cbt = sm + 16 * ZPQ;      // 2 * 1024*20
    const int tid = threadIdx.x;
    const int t   = tid & 127;       // code lane
    const int rg  = tid >> 7;        // row group 0..3
    const int r0  = blockIdx.x * 16;

    for (int i = tid; i < 16 * 128; i += 512) {
        int r = i >> 7, dq = i & 127;
        float4 v = *(const float4*)(zf + (size_t)(r0 + r) * 512 + dq * 4);
        *(float4*)(zs + r * ZPQ + dq * 4) = v;
    }

    float best[4]; int bi[4];
#pragma unroll
    for (int r = 0; r < 4; r++) { best[r] = 3.4e38f; bi[r] = 0; }

    auto stage = [&](int cbase, int dch, int buf) {
        float* dst = cbt + buf * (1024 * CPQ);
        for (int i = tid; i < 4096; i += 512) {
            int c = i >> 2, dq = i & 3;
            float4 v = *(const float4*)(cb + (size_t)(cbase + c) * 512 + dch * 16 + dq * 4);
            *(float4*)(dst + c * CPQ + dq * 4) = v;
        }
    };

    for (int ct = 0; ct < 8; ct++) {
        const int cbase = ct * 1024;
        float acc[4][8];
#pragma unroll
        for (int rr = 0; rr < 4; rr++)
#pragma unroll
            for (int k = 0; k < 8; k++) acc[rr][k] = 0.f;

        __syncthreads();
        stage(cbase, 0, 0);
        for (int dch = 0; dch < 32; dch++) {
            __syncthreads();
            if (dch + 1 < 32) stage(cbase, dch + 1, (dch + 1) & 1);
            const float* cbuf = cbt + (dch & 1) * (1024 * CPQ);
#pragma unroll
            for (int dq = 0; dq < 4; dq++) {
                float4 zv[4];
#pragma unroll
                for (int rr = 0; rr < 4; rr++)
                    zv[rr] = *(const float4*)(zs + (rg * 4 + rr) * ZPQ + dch * 16 + dq * 4);
#pragma unroll
                for (int k = 0; k < 8; k++) {
                    float4 cv = *(const float4*)(cbuf + (k * 128 + t) * CPQ + dq * 4);
#pragma unroll
                    for (int rr = 0; rr < 4; rr++) {
                        float a = acc[rr][k];
                        a = fmaf(zv[rr].x, cv.x, a);
                        a = fmaf(zv[rr].y, cv.y, a);
                        a = fmaf(zv[rr].z, cv.z, a);
                        a = fmaf(zv[rr].w, cv.w, a);
                        acc[rr][k] = a;
                    }
                }
            }
        }
#pragma unroll
        for (int k = 0; k < 8; k++) {
            int cand = cbase + k * 128 + t;
            float nv = cn[cand];
#pragma unroll
            for (int rr = 0; rr < 4; rr++) {
                float s = nv - 2.f * acc[rr][k];
                if (s < best[rr]) { best[rr] = s; bi[rr] = cand; }
            }
        }
    }

    // reduction: 4 independent 128-lane groups (row = r0 + rg*4 + rr)
    float* sv = sm;
    int*   si = (int*)(sm + 512);
    for (int rr = 0; rr < 4; rr++) {
        __syncthreads();
        sv[tid] = best[rr]; si[tid] = bi[rr];
        __syncthreads();
        for (int s = 64; s > 0; s >>= 1) {
            if (t < s) {
                float ov = sv[tid + s]; int oi = si[tid + s];
                if (ov < sv[tid] || (ov == sv[tid] && oi < si[tid])) { sv[tid] = ov; si[tid] = oi; }
            }
            __syncthreads();
        }
        if (t == 0) idx[r0 + rg * 4 + rr] = si[tid];
    }
}

// ---------------- zq gather ----------------
__global__ void __launch_bounds__(256) zqg_k(const float* __restrict__ cb,
                                             const int* __restrict__ idx,
                                             float* __restrict__ zq)
{
    size_t i = (size_t)blockIdx.x * 256 + threadIdx.x;
    if (i >= (size_t)NB * 512 * 32 * 32) return;
    int x = (int)(i & 31);
    int y = (int)((i >> 5) & 31);
    int c = (int)((i >> 10) & 511);
    int bb = (int)(i >> 19);
    int n = bb * 1024 + y * 32 + x;
    zq[i] = cb[(size_t)idx[n] * 512 + c];
}

// ---------------- indices -> tail of output ----------------
__global__ void __launch_bounds__(256) idxout_k(const int* __restrict__ idx,
                                                float* __restrict__ out,
                                                long out_off, long out_size)
{
    int i = blockIdx.x * 256 + threadIdx.x;
    if (i < 16384 && out_off + i < out_size) out[out_off + i] = (float)idx[i];
}

// ---------------- host launcher ----------------
extern "C" void kernel_launch(void* const* d_in, const int* in_sizes, int n_in,
                              void* d_out, int out_size)
{
    const float* x  = (const float*)d_in[0];
    const float* w1 = (const float*)d_in[1];  const float* b1 = (const float*)d_in[2];
    const float* w2 = (const float*)d_in[3];  const float* b2 = (const float*)d_in[4];
    const float* w3 = (const float*)d_in[5];  const float* b3 = (const float*)d_in[6];
    const float* w4 = (const float*)d_in[7];  const float* b4 = (const float*)d_in[8];
    const float* cb = (const float*)d_in[9];
    const float* d1w = (const float*)d_in[10]; const float* d1b = (const float*)d_in[11];
    const float* d2w = (const float*)d_in[12]; const float* d2b = (const float*)d_in[13];
    const float* d3w = (const float*)d_in[14]; const float* d3b = (const float*)d_in[15];
    const float* wo = (const float*)d_in[16]; const float* bo = (const float*)d_in[17];
    float* out = (float*)d_out;

    float *h1, *h2, *h3, *z, *zf, *zq, *g1, *g2, *g3, *cn;
    int* idx;
    cudaGetSymbolAddress((void**)&h1, g_h1);
    cudaGetSymbolAddress((void**)&h2, g_h2);
    cudaGetSymbolAddress((void**)&h3, g_h3);
    cudaGetSymbolAddress((void**)&z,  g_z);
    cudaGetSymbolAddress((void**)&zf, g_zf);
    cudaGetSymbolAddress((void**)&zq, g_zq);
    cudaGetSymbolAddress((void**)&g1, g_g1);
    cudaGetSymbolAddress((void**)&g2, g_g2);
    cudaGetSymbolAddress((void**)&g3, g_g3);
    cudaGetSymbolAddress((void**)&cn, g_cn);
    cudaGetSymbolAddress((void**)&idx, g_idx);

    // codebook norms first (independent)
    cnorm_k<<<1024, 256>>>(cb, cn);

    // Encoder (R6-proven conv8s, CICH=32, TC=8)
    conv8s_k<1, 8, 1><<<dim3( 8, 64, NB), 128>>>(x,  w1, b1, h1,   3,  64, 256, 256, 256, 256);
    conv8s_k<2, 8, 1><<<dim3(16, 16, NB), 128>>>(h1, w2, b2, h2,  64, 128, 256, 256, 128, 128);
    conv8s_k<2, 8, 1><<<dim3(32,  4, NB), 128>>>(h2, w3, b3, h3, 128, 256, 128, 128,  64,  64);
    conv8s_k<2, 8, 0><<<dim3(64,  1, NB), 128>>>(h3, w4, b4, z,  256, 512,  64,  64,  32,  32);

    // Quantize (zt transpose + 16-row blocks for wave balance)
    zt_k<<<512, 256>>>(z, zf);
    const int qsmem = (16 * ZPQ + 2 * 1024 * CPQ) * 4;  // 33280 + 163840 = 197120 B
    cudaFuncSetAttribute(quant16_k, cudaFuncAttributeMaxDynamicSharedMemorySize, qsmem);
    quant16_k<<<1024, 512, qsmem>>>(zf, cb, cn, idx);
    zqg_k<<<(NB * 512 * 32 * 32 + 255) / 256, 256>>>(cb, idx, zq);

    // Decoder (R6-proven deconvS, TC=8)
    deconvS_k<1><<<dim3(32,  4, NB), 128>>>(zq, d1w, d1b, g1, 512, 256,  32,  32);
    deconvS_k<1><<<dim3(16, 16, NB), 128>>>(g1, d2w, d2b, g2, 256, 128,  64,  64);
    deconvS_k<1><<<dim3( 8, 64, NB), 128>>>(g2, d3w, d3b, g3, 128,  64, 128, 128);
    // Final sigmoid conv: 8-wide, TC=3
    conv8s_k<1, 3, 2><<<dim3(1, 64, NB), 128>>>(g3, wo, bo, out, 64, 3, 256, 256, 256, 256);

    // Indices appended after reconstruction
    idxout_k<<<64, 256>>>(idx, out, (long)NB * 3 * 256 * 256, (long)out_size);
}

// round 10
// speedup vs baseline: 1.0578x; 1.0570x over previous
#include <cuda_runtime.h>
#include <math.h>

// ---------------- scratch (device globals; no allocations) ----------------
#define NB 16
__device__ float g_h1[NB*64*256*256];
__device__ float g_h2[NB*128*128*128];
__device__ float g_h3[NB*256*64*64];
__device__ float g_z [NB*512*32*32];
__device__ float g_zf[NB*1024*512];
__device__ float g_zq[NB*512*32*32];
__device__ float g_g1[NB*256*64*64];
__device__ float g_g2[NB*128*128*128];
__device__ float g_g3[NB*64*256*256];
__device__ float g_cn[8192];

// ---------------- 3x3 conv, pad=1, 8-wide, TC output channels ----------------
// Thread: 8 horizontal outputs x TC output channels. Coalesced float4 loads,
// halo via shfl. Weights smem [ci][oc][ky][4] -> one LDS.128 per (oc,row).
// ACT: 0 none, 1 relu, 2 sigmoid
template<int STRIDE, int TC, int ACT>
__global__ void __launch_bounds__(128) conv8s_k(
    const float* __restrict__ in, const float* __restrict__ wgt,
    const float* __restrict__ bias, float* __restrict__ out,
    int Cin, int Cout, int Hin, int Win, int Hout, int Wout)
{
    constexpr int CICH = 32;
    constexpr int NW = (STRIDE == 1) ? 10 : 17;
    __shared__ float wsf[CICH * TC * 12];

    const int tid  = threadIdx.x;
    const int W8   = Wout >> 3;
    const int rows = 128 / W8;
    const int q    = tid % W8;
    const int oy   = blockIdx.y * rows + tid / W8;
    const int ox0  = q * 8;
    const int ocg  = blockIdx.x * TC;
    const int n    = blockIdx.z;

    float acc[TC][8];
#pragma unroll
    for (int o = 0; o < TC; o++)
#pragma unroll
        for (int j = 0; j < 8; j++) acc[o][j] = 0.f;

    bool rval[3]; int iyo[3];
#pragma unroll
    for (int ky = 0; ky < 3; ky++) {
        int iy = oy * STRIDE + ky - 1;
        rval[ky] = (iy >= 0 && iy < Hin);
        iyo[ky] = iy < 0 ? 0 : (iy >= Hin ? Hin - 1 : iy);
    }

    auto loadRow = [&](float (&w)[NW], int cabs, int ky) {
        const float* rp = in + ((size_t)(n * Cin + cabs) * Hin + iyo[ky]) * Win;
        if (STRIDE == 1) {
            float4 a = *(const float4*)(rp + ox0);
            float4 b = *(const float4*)(rp + ox0 + 4);
            float lft = __shfl_up_sync(0xffffffffu, b.w, 1);
            float rgt = __shfl_down_sync(0xffffffffu, a.x, 1);
            if (q == 0) lft = 0.f;
            if (q == W8 - 1) rgt = 0.f;
            w[0]=lft; w[1]=a.x; w[2]=a.y; w[3]=a.z; w[4]=a.w;
            w[5]=b.x; w[6]=b.y; w[7]=b.z; w[8]=b.w; w[9]=rgt;
        } else {
            const int ib = ox0 * 2;
            float4 a = *(const float4*)(rp + ib);
            float4 b = *(const float4*)(rp + ib + 4);
            float4 c = *(const float4*)(rp + ib + 8);
            float4 d = *(const float4*)(rp + ib + 12);
            float lft = __shfl_up_sync(0xffffffffu, d.w, 1);
            if (q == 0) lft = 0.f;
            w[0]=lft;
            w[1]=a.x; w[2]=a.y; w[3]=a.z; w[4]=a.w;
            w[5]=b.x; w[6]=b.y; w[7]=b.z; w[8]=b.w;
            w[9]=c.x; w[10]=c.y; w[11]=c.z; w[12]=c.w;
            w[13]=d.x; w[14]=d.y; w[15]=d.z; w[16]=d.w;
        }
        if (!rval[ky]) {
#pragma unroll
            for (int i = 0; i < NW; i++) w[i] = 0.f;
        }
    };

    auto computeRow = [&](float (&w)[NW], int ci, int ky) {
#pragma unroll
        for (int oc = 0; oc < TC; oc++) {
            const float4 wv = *(const float4*)(wsf + (ci * TC + oc) * 12 + ky * 4);
#pragma unroll
            for (int j = 0; j < 8; j++) {
                float a = acc[oc][j];
                a = fmaf(w[j * STRIDE + 0], wv.x, a);
                a = fmaf(w[j * STRIDE + 1], wv.y, a);
                a = fmaf(w[j * STRIDE + 2], wv.z, a);
                acc[oc][j] = a;
            }
        }
    };

    float bufA[NW], bufB[NW];
    for (int cc = 0; cc < Cin; cc += CICH) {
        const int chunk = min(CICH, Cin - cc);
        __syncthreads();
        for (int i = tid; i < chunk * TC * 9; i += 128) {
            int ci = i / (TC * 9);
            int r  = i - ci * (TC * 9);
            int oc = r / 9;
            int k  = r - oc * 9;
            wsf[(ci * TC + oc) * 12 + (k / 3) * 4 + (k % 3)] =
                wgt[(size_t)(ocg + oc) * Cin * 9 + (size_t)(cc + ci) * 9 + k];
        }
        __syncthreads();
        const int total = chunk * 3;
        loadRow(bufA, cc, 0);
        for (int m = 0; m < total; m++) {
            const int mn = m + 1;
            if (m & 1) {
                if (mn < total) loadRow(bufA, cc + mn / 3, mn % 3);
                computeRow(bufB, m / 3, m % 3);
            } else {
                if (mn < total) loadRow(bufB, cc + mn / 3, mn % 3);
                computeRow(bufA, m / 3, m % 3);
            }
        }
    }

#pragma unroll
    for (int oc = 0; oc < TC; oc++) {
        float bv = bias[ocg + oc];
        float* op = out + (((size_t)n * Cout + ocg + oc) * Hout + oy) * Wout + ox0;
        float v[8];
#pragma unroll
        for (int j = 0; j < 8; j++) {
            float a = acc[oc][j] + bv;
            if (ACT == 1) a = a > 0.f ? a : 0.f;
            if (ACT == 2) a = 1.f / (1.f + expf(-a));
            v[j] = a;
        }
        *(float4*)(op)     = make_float4(v[0], v[1], v[2], v[3]);
        *(float4*)(op + 4) = make_float4(v[4], v[5], v[6], v[7]);
    }
}

// ---------------- transposed conv k=3 s=2 p=1 op=1, scalar, TC=8 --------------
template<int ACT>
__global__ void __launch_bounds__(128) deconvS_k(
    const float* __restrict__ in, const float* __restrict__ wgt,  // [Cin][Cout][3][3]
    const float* __restrict__ bias, float* __restrict__ out,
    int Cin, int Cout, int Hin, int Win)
{
    constexpr int CICH = 32;
    constexpr int TC = 8;
    __shared__ float wsf[CICH * TC * 12];

    const int Hout = Hin * 2, Wout = Win * 2;
    const int tid  = threadIdx.x;
    const int W4   = Wout >> 2;
    const int rows = 128 / W4;
    const int q    = tid % W4;
    const int a    = blockIdx.y * rows + tid / W4;
    const int b    = q * 2;
    const int ocg  = blockIdx.x * TC;
    const int n    = blockIdx.z;

    const bool v_a1 = (a + 1) < Hin;
    const bool v_b2 = (b + 2) < Win;

    float acc[TC][8];
#pragma unroll
    for (int o = 0; o < TC; o++)
#pragma unroll
        for (int j = 0; j < 8; j++) acc[o][j] = 0.f;

    auto loadRaw = [&](float (&rw)[6], int cabs) {
        const float* ip = in + ((size_t)n * Cin + cabs) * Hin * Win;
        const float* r0 = ip + (size_t)a * Win + b;
        float2 p0 = *(const float2*)r0;
        rw[0] = p0.x; rw[1] = p0.y;
        rw[2] = v_b2 ? r0[2] : 0.f;
        if (v_a1) {
            const float* r1 = r0 + Win;
            float2 p1 = *(const float2*)r1;
            rw[3] = p1.x; rw[4] = p1.y; rw[5] = v_b2 ? r1[2] : 0.f;
        } else {
            rw[3] = 0.f; rw[4] = 0.f; rw[5] = 0.f;
        }
    };
    auto computeCi = [&](float (&rw)[6], int ci) {
        float i00 = rw[0], i01 = rw[1], i02 = rw[2];
        float i10 = rw[3], i11 = rw[4], i12 = rw[5];
#pragma unroll
        for (int oc = 0; oc < TC; oc++) {
            const float* wp = wsf + (ci * TC + oc) * 12;
            const float4 A = *(const float4*)(wp);
            const float4 B = *(const float4*)(wp + 4);
            const float w22 = wp[8];
            float w00=A.x, w01=A.y, w02=A.z, w10=A.w;
            float w11=B.x, w12=B.y, w20=B.z, w21=B.w;
            acc[oc][0] = fmaf(i00, w11, acc[oc][0]);
            acc[oc][1] = fmaf(i00, w12, fmaf(i01, w10, acc[oc][1]));
            acc[oc][2] = fmaf(i01, w11, acc[oc][2]);
            acc[oc][3] = fmaf(i01, w12, fmaf(i02, w10, acc[oc][3]));
            acc[oc][4] = fmaf(i00, w21, fmaf(i10, w01, acc[oc][4]));
            acc[oc][5] = fmaf(i00, w22, fmaf(i01, w20, fmaf(i10, w02, fmaf(i11, w00, acc[oc][5]))));
            acc[oc][6] = fmaf(i01, w21, fmaf(i11, w01, acc[oc][6]));
            acc[oc][7] = fmaf(i01, w22, fmaf(i02, w20, fmaf(i11, w02, fmaf(i12, w00, acc[oc][7]))));
        }
    };

    float rawA[6], rawB[6];
    for (int cc = 0; cc < Cin; cc += CICH) {
        const int chunk = min(CICH, Cin - cc);
        __syncthreads();
        for (int i = tid; i < chunk * TC * 9; i += 128) {
            int ci = i / (TC * 9);
            int r  = i - ci * (TC * 9);
            int oc = r / 9;
            int k  = r - oc * 9;
            wsf[(ci * TC + oc) * 12 + k] =
                wgt[(size_t)(cc + ci) * Cout * 9 + (size_t)(ocg + oc) * 9 + k];
        }
        __syncthreads();
        loadRaw(rawA, cc);
        for (int ci = 0; ci < chunk; ci += 2) {
            if (ci + 1 < chunk) loadRaw(rawB, cc + ci + 1);
            computeCi(rawA, ci);
            if (ci + 2 < chunk) loadRaw(rawA, cc + ci + 2);
            if (ci + 1 < chunk) computeCi(rawB, ci + 1);
        }
    }

#pragma unroll
    for (int oc = 0; oc < TC; oc++) {
        float bv = bias[ocg + oc];
        float* op = out + (((size_t)n * Cout + ocg + oc) * Hout + 2 * a) * Wout + 4 * q;
        float v0[4], v1[4];
#pragma unroll
        for (int j = 0; j < 4; j++) {
            float x0 = acc[oc][j] + bv;
            float x1 = acc[oc][4 + j] + bv;
            if (ACT == 1) { x0 = x0 > 0.f ? x0 : 0.f; x1 = x1 > 0.f ? x1 : 0.f; }
            v0[j] = x0; v1[j] = x1;
        }
        *(float4*)(op)        = make_float4(v0[0], v0[1], v0[2], v0[3]);
        *(float4*)(op + Wout) = make_float4(v1[0], v1[1], v1[2], v1[3]);
    }
}

// ---------------- z [B,512,32,32] -> zf [16384, 512] ----------------
__global__ void __launch_bounds__(256) zt_k(const float* __restrict__ z,
                                            float* __restrict__ zf)
{
    __shared__ float t[128 * 33];
    const int blk = blockIdx.x;
    const int bb  = blk >> 5;
    const int y   = blk & 31;
    const int tid = threadIdx.x;
    for (int cc = 0; cc < 512; cc += 128) {
        __syncthreads();
        for (int i = tid; i < 128 * 32; i += 256) {
            int c = i >> 5, x = i & 31;
            t[c * 33 + x] = z[(((size_t)bb * 512 + cc + c) * 32 + y) * 32 + x];
        }
        __syncthreads();
        for (int i = tid; i < 32 * 128; i += 256) {
            int x = i >> 7, c = i & 127;
            zf[((size_t)bb * 1024 + y * 32 + x) * 512 + cc + c] = t[c * 33 + x];
        }
    }
}

// ---------------- codebook row norms ----------------
__global__ void __launch_bounds__(256) cnorm_k(const float* __restrict__ cb,
                                               float* __restrict__ cn)
{
    const int warp = threadIdx.x >> 5, lane = threadIdx.x & 31;
    const int code = blockIdx.x * 8 + warp;
    const float* p = cb + (size_t)code * 512;
    float s = 0.f;
    for (int d = lane; d < 512; d += 32) { float v = p[d]; s = fmaf(v, v, s); }
#pragma unroll
    for (int o = 16; o > 0; o >>= 1) s += __shfl_xor_sync(0xffffffffu, s, o);
    if (lane == 0) cn[code] = s;
}

// ---------------- quantizer: 32 rows/block, thread = 8 rows x 8 codes ---------
// R6-proven core. Fused epilogue: block owns exactly one (b,y) pixel row
// (32 pixels), so it writes zq and the float index tail directly.
// smem: zs [32][520] (66.6KB), cbt double-buffered [2][1024][20] (160KB)
#define ZPQ 520
#define CPQ 20
__global__ void __launch_bounds__(512) quant8_k(const float* __restrict__ zf,
                                                const float* __restrict__ cb,
                                                const float* __restrict__ cn,
                                                float* __restrict__ zq,
                                                float* __restrict__ out,
                                                long out_off, long out_size)
{
    extern __shared__ float sm[];
    float* zs  = sm;                 // 32*520
    float* cbt = sm + 32 * ZPQ;      // 2 * 1024*20
    const int tid = threadIdx.x;
    const int t   = tid & 127;       // code lane
    const int rg  = tid >> 7;        // row group 0..3
    const int r0  = blockIdx.x * 32;
    const int bb  = r0 >> 10;        // batch of this pixel row
    const int y   = (r0 >> 5) & 31;  // spatial row

    for (int i = tid; i < 32 * 128; i += 512) {
        int r = i >> 7, dq = i & 127;
        float4 v = *(const float4*)(zf + (size_t)(r0 + r) * 512 + dq * 4);
        *(float4*)(zs + r * ZPQ + dq * 4) = v;
    }

    float best[8]; int bi[8];
#pragma unroll
    for (int r = 0; r < 8; r++) { best[r] = 3.4e38f; bi[r] = 0; }

    auto stage = [&](int cbase, int dch, int buf) {
        float* dst = cbt + buf * (1024 * CPQ);
        for (int i = tid; i < 4096; i += 512) {
            int c = i >> 2, dq = i & 3;
            float4 v = *(const float4*)(cb + (size_t)(cbase + c) * 512 + dch * 16 + dq * 4);
            *(float4*)(dst + c * CPQ + dq * 4) = v;
        }
    };

    for (int ct = 0; ct < 8; ct++) {
        const int cbase = ct * 1024;
        float acc[8][8];
#pragma unroll
        for (int rr = 0; rr < 8; rr++)
#pragma unroll
            for (int k = 0; k < 8; k++) acc[rr][k] = 0.f;

        __syncthreads();
        stage(cbase, 0, 0);
        for (int dch = 0; dch < 32; dch++) {
            __syncthreads();
            if (dch + 1 < 32) stage(cbase, dch + 1, (dch + 1) & 1);
            const float* cbuf = cbt + (dch & 1) * (1024 * CPQ);
#pragma unroll
            for (int dq = 0; dq < 4; dq++) {
                float4 zv[8];
#pragma unroll
                for (int rr = 0; rr < 8; rr++)
                    zv[rr] = *(const float4*)(zs + (rg * 8 + rr) * ZPQ + dch * 16 + dq * 4);
#pragma unroll
                for (int k = 0; k < 8; k++) {
                    float4 cv = *(const float4*)(cbuf + (k * 128 + t) * CPQ + dq * 4);
#pragma unroll
                    for (int rr = 0; rr < 8; rr++) {
                        float a = acc[rr][k];
                        a = fmaf(zv[rr].x, cv.x, a);
                        a = fmaf(zv[rr].y, cv.y, a);
                        a = fmaf(zv[rr].z, cv.z, a);
                        a = fmaf(zv[rr].w, cv.w, a);
                        acc[rr][k] = a;
                    }
                }
            }
        }
#pragma unroll
        for (int k = 0; k < 8; k++) {
            int cand = cbase + k * 128 + t;
            float nv = cn[cand];
#pragma unroll
            for (int rr = 0; rr < 8; rr++) {
                float s = nv - 2.f * acc[rr][k];
                if (s < best[rr]) { best[rr] = s; bi[rr] = cand; }
            }
        }
    }

    // reduction: 4 independent 128-lane groups (row rg*8 + rr); lowest index on ties
    float* sv = sm;
    int*   si = (int*)(sm + 512);
    int*   ridx = (int*)(sm + 1024);  // 32 chosen indices (x = local row)
    for (int rr = 0; rr < 8; rr++) {
        __syncthreads();
        sv[tid] = best[rr]; si[tid] = bi[rr];
        __syncthreads();
        for (int s = 64; s > 0; s >>= 1) {
            if (t < s) {
                float ov = sv[tid + s]; int oi = si[tid + s];
                if (ov < sv[tid] || (ov == sv[tid] && oi < si[tid])) { sv[tid] = ov; si[tid] = oi; }
            }
            __syncthreads();
        }
        if (t == 0) ridx[rg * 8 + rr] = si[tid];
    }
    __syncthreads();

    // fused epilogue: index tail (as float) + zq gather for this pixel row
    if (tid < 32) {
        long o = out_off + r0 + tid;
        if (o < out_size) out[o] = (float)ridx[tid];
    }
    for (int i = tid; i < 512 * 32; i += 512) {
        int c = i >> 5, x = i & 31;
        zq[(((size_t)bb * 512 + c) * 32 + y) * 32 + x] = cb[(size_t)ridx[x] * 512 + c];
    }
}

// ---------------- host launcher ----------------
extern "C" void kernel_launch(void* const* d_in, const int* in_sizes, int n_in,
                              void* d_out, int out_size)
{
    const float* x  = (const float*)d_in[0];
    const float* w1 = (const float*)d_in[1];  const float* b1 = (const float*)d_in[2];
    const float* w2 = (const float*)d_in[3];  const float* b2 = (const float*)d_in[4];
    const float* w3 = (const float*)d_in[5];  const float* b3 = (const float*)d_in[6];
    const float* w4 = (const float*)d_in[7];  const float* b4 = (const float*)d_in[8];
    const float* cb = (const float*)d_in[9];
    const float* d1w = (const float*)d_in[10]; const float* d1b = (const float*)d_in[11];
    const float* d2w = (const float*)d_in[12]; const float* d2b = (const float*)d_in[13];
    const float* d3w = (const float*)d_in[14]; const float* d3b = (const float*)d_in[15];
    const float* wo = (const float*)d_in[16]; const float* bo = (const float*)d_in[17];
    float* out = (float*)d_out;

    float *h1, *h2, *h3, *z, *zf, *zq, *g1, *g2, *g3, *cn;
    cudaGetSymbolAddress((void**)&h1, g_h1);
    cudaGetSymbolAddress((void**)&h2, g_h2);
    cudaGetSymbolAddress((void**)&h3, g_h3);
    cudaGetSymbolAddress((void**)&z,  g_z);
    cudaGetSymbolAddress((void**)&zf, g_zf);
    cudaGetSymbolAddress((void**)&zq, g_zq);
    cudaGetSymbolAddress((void**)&g1, g_g1);
    cudaGetSymbolAddress((void**)&g2, g_g2);
    cudaGetSymbolAddress((void**)&g3, g_g3);
    cudaGetSymbolAddress((void**)&cn, g_cn);

    // codebook norms first (independent)
    cnorm_k<<<1024, 256>>>(cb, cn);

    // Encoder (R6-proven conv8s, CICH=32, TC=8)
    conv8s_k<1, 8, 1><<<dim3( 8, 64, NB), 128>>>(x,  w1, b1, h1,   3,  64, 256, 256, 256, 256);
    conv8s_k<2, 8, 1><<<dim3(16, 16, NB), 128>>>(h1, w2, b2, h2,  64, 128, 256, 256, 128, 128);
    conv8s_k<2, 8, 1><<<dim3(32,  4, NB), 128>>>(h2, w3, b3, h3, 128, 256, 128, 128,  64,  64);
    conv8s_k<2, 8, 0><<<dim3(64,  1, NB), 128>>>(h3, w4, b4, z,  256, 512,  64,  64,  32,  32);

    // Quantize (R6-proven quant8_k with fused zq gather + index-tail write)
    zt_k<<<512, 256>>>(z, zf);
    const int qsmem = (32 * ZPQ + 2 * 1024 * CPQ) * 4;  // 230400 B
    cudaFuncSetAttribute(quant8_k, cudaFuncAttributeMaxDynamicSharedMemorySize, qsmem);
    quant8_k<<<512, 512, qsmem>>>(zf, cb, cn, zq, out,
                                  (long)NB * 3 * 256 * 256, (long)out_size);

    // Decoder (R6-proven deconvS, TC=8)
    deconvS_k<1><<<dim3(32,  4, NB), 128>>>(zq, d1w, d1b, g1, 512, 256,  32,  32);
    deconvS_k<1><<<dim3(16, 16, NB), 128>>>(g1, d2w, d2b, g2, 256, 128,  64,  64);
    deconvS_k<1><<<dim3( 8, 64, NB), 128>>>(g2, d3w, d3b, g3, 128,  64, 128, 128);
    // Final sigmoid conv: 8-wide, TC=3
    conv8s_k<1, 3, 2><<<dim3(1, 64, NB), 128>>>(g3, wo, bo, out, 64, 3, 256, 256, 256, 256);
}

// round 12
// speedup vs baseline: 1.1096x; 1.0489x over previous
#include <cuda_runtime.h>
#include <cuda_bf16.h>
#include <mma.h>
#include <cstdint>
#include <math.h>

using namespace nvcuda;

// ---------------- scratch (device globals; no allocations) ----------------
#define NB 16
__device__ float g_h1[NB*64*256*256];
__device__ float g_h2[NB*128*128*128];
__device__ float g_h3[NB*256*64*64];
__device__ float g_z [NB*512*32*32];
__device__ float g_zf[NB*1024*512];
__device__ float g_g3[NB*64*256*256];
__device__ float g_cn[8192];
__device__ __nv_bfloat16 g_zqh[16384*512];
__device__ __nv_bfloat16 g_zql[16384*512];
__device__ __nv_bfloat16 g_g1h[NB*64*64*256];
__device__ __nv_bfloat16 g_g1l[NB*64*64*256];
__device__ __nv_bfloat16 g_g2h[NB*128*128*128];
__device__ __nv_bfloat16 g_g2l[NB*128*128*128];
__device__ __nv_bfloat16 g_w1h[9*256*512];
__device__ __nv_bfloat16 g_w1l[9*256*512];
__device__ __nv_bfloat16 g_w2h[9*128*256];
__device__ __nv_bfloat16 g_w2l[9*128*256];
__device__ __nv_bfloat16 g_w3h[9*64*128];
__device__ __nv_bfloat16 g_w3l[9*64*128];

// ---------------- 3x3 conv, pad=1, 8-wide, TC output channels ----------------
template<int STRIDE, int TC, int ACT>
__global__ void __launch_bounds__(128) conv8s_k(
    const float* __restrict__ in, const float* __restrict__ wgt,
    const float* __restrict__ bias, float* __restrict__ out,
    int Cin, int Cout, int Hin, int Win, int Hout, int Wout)
{
    constexpr int CICH = 32;
    constexpr int NW = (STRIDE == 1) ? 10 : 17;
    __shared__ float wsf[CICH * TC * 12];

    const int tid  = threadIdx.x;
    const int W8   = Wout >> 3;
    const int rows = 128 / W8;
    const int q    = tid % W8;
    const int oy   = blockIdx.y * rows + tid / W8;
    const int ox0  = q * 8;
    const int ocg  = blockIdx.x * TC;
    const int n    = blockIdx.z;

    float acc[TC][8];
#pragma unroll
    for (int o = 0; o < TC; o++)
#pragma unroll
        for (int j = 0; j < 8; j++) acc[o][j] = 0.f;

    bool rval[3]; int iyo[3];
#pragma unroll
    for (int ky = 0; ky < 3; ky++) {
        int iy = oy * STRIDE + ky - 1;
        rval[ky] = (iy >= 0 && iy < Hin);
        iyo[ky] = iy < 0 ? 0 : (iy >= Hin ? Hin - 1 : iy);
    }

    auto loadRow = [&](float (&w)[NW], int cabs, int ky) {
        const float* rp = in + ((size_t)(n * Cin + cabs) * Hin + iyo[ky]) * Win;
        if (STRIDE == 1) {
            float4 a = *(const float4*)(rp + ox0);
            float4 b = *(const float4*)(rp + ox0 + 4);
            float lft = __shfl_up_sync(0xffffffffu, b.w, 1);
            float rgt = __shfl_down_sync(0xffffffffu, a.x, 1);
            if (q == 0) lft = 0.f;
            if (q == W8 - 1) rgt = 0.f;
            w[0]=lft; w[1]=a.x; w[2]=a.y; w[3]=a.z; w[4]=a.w;
            w[5]=b.x; w[6]=b.y; w[7]=b.z; w[8]=b.w; w[9]=rgt;
        } else {
            const int ib = ox0 * 2;
            float4 a = *(const float4*)(rp + ib);
            float4 b = *(const float4*)(rp + ib + 4);
            float4 c = *(const float4*)(rp + ib + 8);
            float4 d = *(const float4*)(rp + ib + 12);
            float lft = __shfl_up_sync(0xffffffffu, d.w, 1);
            if (q == 0) lft = 0.f;
            w[0]=lft;
            w[1]=a.x; w[2]=a.y; w[3]=a.z; w[4]=a.w;
            w[5]=b.x; w[6]=b.y; w[7]=b.z; w[8]=b.w;
            w[9]=c.x; w[10]=c.y; w[11]=c.z; w[12]=c.w;
            w[13]=d.x; w[14]=d.y; w[15]=d.z; w[16]=d.w;
        }
        if (!rval[ky]) {
#pragma unroll
            for (int i = 0; i < NW; i++) w[i] = 0.f;
        }
    };

    auto computeRow = [&](float (&w)[NW], int ci, int ky) {
#pragma unroll
        for (int oc = 0; oc < TC; oc++) {
            const float4 wv = *(const float4*)(wsf + (ci * TC + oc) * 12 + ky * 4);
#pragma unroll
            for (int j = 0; j < 8; j++) {
                float a = acc[oc][j];
                a = fmaf(w[j * STRIDE + 0], wv.x, a);
                a = fmaf(w[j * STRIDE + 1], wv.y, a);
                a = fmaf(w[j * STRIDE + 2], wv.z, a);
                acc[oc][j] = a;
            }
        }
    };

    float bufA[NW], bufB[NW];
    for (int cc = 0; cc < Cin; cc += CICH) {
        const int chunk = min(CICH, Cin - cc);
        __syncthreads();
        for (int i = tid; i < chunk * TC * 9; i += 128) {
            int ci = i / (TC * 9);
            int r  = i - ci * (TC * 9);
            int oc = r / 9;
            int k  = r - oc * 9;
            wsf[(ci * TC + oc) * 12 + (k / 3) * 4 + (k % 3)] =
                wgt[(size_t)(ocg + oc) * Cin * 9 + (size_t)(cc + ci) * 9 + k];
        }
        __syncthreads();
        const int total = chunk * 3;
        loadRow(bufA, cc, 0);
        for (int m = 0; m < total; m++) {
            const int mn = m + 1;
            if (m & 1) {
                if (mn < total) loadRow(bufA, cc + mn / 3, mn % 3);
                computeRow(bufB, m / 3, m % 3);
            } else {
                if (mn < total) loadRow(bufB, cc + mn / 3, mn % 3);
                computeRow(bufA, m / 3, m % 3);
            }
        }
    }

#pragma unroll
    for (int oc = 0; oc < TC; oc++) {
        float bv = bias[ocg + oc];
        float* op = out + (((size_t)n * Cout + ocg + oc) * Hout + oy) * Wout + ox0;
        float v[8];
#pragma unroll
        for (int j = 0; j < 8; j++) {
            float a = acc[oc][j] + bv;
            if (ACT == 1) a = a > 0.f ? a : 0.f;
            if (ACT == 2) a = 1.f / (1.f + expf(-a));
            v[j] = a;
        }
        *(float4*)(op)     = make_float4(v[0], v[1], v[2], v[3]);
        *(float4*)(op + 4) = make_float4(v[4], v[5], v[6], v[7]);
    }
}

// ---------------- z [B,512,32,32] -> zf [16384, 512] ----------------
__global__ void __launch_bounds__(256) zt_k(const float* __restrict__ z,
                                            float* __restrict__ zf)
{
    __shared__ float t[128 * 33];
    const int blk = blockIdx.x;
    const int bb  = blk >> 5;
    const int y   = blk & 31;
    const int tid = threadIdx.x;
    for (int cc = 0; cc < 512; cc += 128) {
        __syncthreads();
        for (int i = tid; i < 128 * 32; i += 256) {
            int c = i >> 5, x = i & 31;
            t[c * 33 + x] = z[(((size_t)bb * 512 + cc + c) * 32 + y) * 32 + x];
        }
        __syncthreads();
        for (int i = tid; i < 32 * 128; i += 256) {
            int x = i >> 7, c = i & 127;
            zf[((size_t)bb * 1024 + y * 32 + x) * 512 + cc + c] = t[c * 33 + x];
        }
    }
}

// ---------------- codebook row norms ----------------
__global__ void __launch_bounds__(256) cnorm_k(const float* __restrict__ cb,
                                               float* __restrict__ cn)
{
    const int warp = threadIdx.x >> 5, lane = threadIdx.x & 31;
    const int code = blockIdx.x * 8 + warp;
    const float* p = cb + (size_t)code * 512;
    float s = 0.f;
    for (int d = lane; d < 512; d += 32) { float v = p[d]; s = fmaf(v, v, s); }
#pragma unroll
    for (int o = 16; o > 0; o >>= 1) s += __shfl_xor_sync(0xffffffffu, s, o);
    if (lane == 0) cn[code] = s;
}

// ---------------- generic weight split: w [Cin][Cout][3][3] -> hi/lo [tap][oc][ci]
__global__ void __launch_bounds__(256) wprep_k(const float* __restrict__ w,
                                               __nv_bfloat16* __restrict__ bh,
                                               __nv_bfloat16* __restrict__ bl,
                                               int Cin, int Cout)
{
    int i = blockIdx.x * 256 + threadIdx.x;
    if (i >= 9 * Cin * Cout) return;
    int ci  = i % Cin;
    int r   = i / Cin;
    int oc  = r % Cout;
    int tap = r / Cout;
    float v = w[((size_t)ci * Cout + oc) * 9 + tap];
    __nv_bfloat16 h = __float2bfloat16(v);
    float rr = v - __bfloat162float(h);
    bh[((size_t)tap * Cout + oc) * Cin + ci] = h;
    bl[((size_t)tap * Cout + oc) * Cin + ci] = __float2bfloat16(rr);
}

// ---------------- quantizer: R10 core + epilogue writes zq as bf16 hi/lo ------
#define ZPQ 520
#define CPQ 20
__global__ void __launch_bounds__(512) quant8_k(const float* __restrict__ zf,
                                                const float* __restrict__ cb,
                                                const float* __restrict__ cn,
                                                __nv_bfloat16* __restrict__ zqh,
                                                __nv_bfloat16* __restrict__ zql,
                                                float* __restrict__ out,
                                                long out_off, long out_size)
{
    extern __shared__ float sm[];
    float* zs  = sm;
    float* cbt = sm + 32 * ZPQ;
    const int tid = threadIdx.x;
    const int t   = tid & 127;
    const int rg  = tid >> 7;
    const int r0  = blockIdx.x * 32;
    const int bb  = r0 >> 10;
    const int y   = (r0 >> 5) & 31;

    for (int i = tid; i < 32 * 128; i += 512) {
        int r = i >> 7, dq = i & 127;
        float4 v = *(const float4*)(zf + (size_t)(r0 + r) * 512 + dq * 4);
        *(float4*)(zs + r * ZPQ + dq * 4) = v;
    }

    float best[8]; int bi[8];
#pragma unroll
    for (int r = 0; r < 8; r++) { best[r] = 3.4e38f; bi[r] = 0; }

    auto stage = [&](int cbase, int dch, int buf) {
        float* dst = cbt + buf * (1024 * CPQ);
        for (int i = tid; i < 4096; i += 512) {
            int c = i >> 2, dq = i & 3;
            float4 v = *(const float4*)(cb + (size_t)(cbase + c) * 512 + dch * 16 + dq * 4);
            *(float4*)(dst + c * CPQ + dq * 4) = v;
        }
    };

    for (int ct = 0; ct < 8; ct++) {
        const int cbase = ct * 1024;
        float acc[8][8];
#pragma unroll
        for (int rr = 0; rr < 8; rr++)
#pragma unroll
            for (int k = 0; k < 8; k++) acc[rr][k] = 0.f;

        __syncthreads();
        stage(cbase, 0, 0);
        for (int dch = 0; dch < 32; dch++) {
            __syncthreads();
            if (dch + 1 < 32) stage(cbase, dch + 1, (dch + 1) & 1);
            const float* cbuf = cbt + (dch & 1) * (1024 * CPQ);
#pragma unroll
            for (int dq = 0; dq < 4; dq++) {
                float4 zv[8];
#pragma unroll
                for (int rr = 0; rr < 8; rr++)
                    zv[rr] = *(const float4*)(zs + (rg * 8 + rr) * ZPQ + dch * 16 + dq * 4);
#pragma unroll
                for (int k = 0; k < 8; k++) {
                    float4 cv = *(const float4*)(cbuf + (k * 128 + t) * CPQ + dq * 4);
#pragma unroll
                    for (int rr = 0; rr < 8; rr++) {
                        float a = acc[rr][k];
                        a = fmaf(zv[rr].x, cv.x, a);
                        a = fmaf(zv[rr].y, cv.y, a);
                        a = fmaf(zv[rr].z, cv.z, a);
                        a = fmaf(zv[rr].w, cv.w, a);
                        acc[rr][k] = a;
                    }
                }
            }
        }
#pragma unroll
        for (int k = 0; k < 8; k++) {
            int cand = cbase + k * 128 + t;
            float nv = cn[cand];
#pragma unroll
            for (int rr = 0; rr < 8; rr++) {
                float s = nv - 2.f * acc[rr][k];
                if (s < best[rr]) { best[rr] = s; bi[rr] = cand; }
            }
        }
    }

    float* sv = sm;
    int*   si = (int*)(sm + 512);
    int*   ridx = (int*)(sm + 1024);
    for (int rr = 0; rr < 8; rr++) {
        __syncthreads();
        sv[tid] = best[rr]; si[tid] = bi[rr];
        __syncthreads();
        for (int s = 64; s > 0; s >>= 1) {
            if (t < s) {
                float ov = sv[tid + s]; int oi = si[tid + s];
                if (ov < sv[tid] || (ov == sv[tid] && oi < si[tid])) { sv[tid] = ov; si[tid] = oi; }
            }
            __syncthreads();
        }
        if (t == 0) ridx[rg * 8 + rr] = si[tid];
    }
    __syncthreads();

    if (tid < 32) {
        long o = out_off + r0 + tid;
        if (o < out_size) out[o] = (float)ridx[tid];
    }
    for (int i = tid; i < 32 * 512; i += 512) {
        int x = i >> 9, c = i & 511;
        float v = cb[(size_t)ridx[x] * 512 + c];
        __nv_bfloat16 h = __float2bfloat16(v);
        float r = v - __bfloat162float(h);
        size_t px = (size_t)bb * 1024 + y * 32 + x;
        zqh[px * 512 + c] = h;
        zql[px * 512 + c] = __float2bfloat16(r);
    }
}

// ---------------- deconv via WMMA split-bf16 polyphase GEMM ----------------
// CTA tile: M=128 px (4 rows x 32 cols at (y0,x0)), N = NT = NFRAG*32 ocs.
// For each class (dy,dx): D = sum over taps x 3 splits x K-chunks of A[px][ci]*B[oc][ci]^T.
// OUTF=0: emit bf16 hi/lo channels-last (relu). OUTF=1: emit f32 NCHW (relu).
template<int NFRAG, int OUTF>
__global__ void __launch_bounds__(256) deconvW_k(
    const __nv_bfloat16* __restrict__ inH, const __nv_bfloat16* __restrict__ inL,
    const __nv_bfloat16* __restrict__ wH,  const __nv_bfloat16* __restrict__ wL,
    const float* __restrict__ bias,
    __nv_bfloat16* __restrict__ outH, __nv_bfloat16* __restrict__ outL,
    float* __restrict__ outF,
    int Cin, int Cout, int Hin, int Win, int ytiles, int xtiles, int nch)
{
    constexpr int NT = NFRAG * 32;
    extern __shared__ char smem[];
    __nv_bfloat16* As = (__nv_bfloat16*)smem;             // 128 x 72 (pitch 144B)
    __nv_bfloat16* Bs = (__nv_bfloat16*)(smem + 18432);   // NT x 72
    float* Cs = (float*)smem;                              // 128 x (NT+8)
    const int ldC = NT + 8;

    const int tid = threadIdx.x, wid = tid >> 5;
    const int wm = wid >> 1, wn = wid & 1;

    int b = blockIdx.x;
    const int och = b % nch; b /= nch;
    const int x0  = (b % xtiles) * 32; b /= xtiles;
    const int y0  = (b % ytiles) * 4;  b /= ytiles;
    const int n   = b;
    const int Hout = Hin * 2, Wout = Win * 2;
    const int nkc = Cin >> 6;

    for (int cls = 0; cls < 4; cls++) {
        const int dy = cls >> 1, dx = cls & 1;
        int kys[2], sys[2], nky, kxs[2], sxs[2], nkx;
        if (dy == 0) { kys[0]=1; sys[0]=0; nky=1; }
        else         { kys[0]=2; sys[0]=0; kys[1]=0; sys[1]=1; nky=2; }
        if (dx == 0) { kxs[0]=1; sxs[0]=0; nkx=1; }
        else         { kxs[0]=2; sxs[0]=0; kxs[1]=0; sxs[1]=1; nkx=2; }

        wmma::fragment<wmma::accumulator, 16, 16, 16, float> acc[2][NFRAG];
#pragma unroll
        for (int mf = 0; mf < 2; mf++)
#pragma unroll
            for (int nf = 0; nf < NFRAG; nf++) wmma::fill_fragment(acc[mf][nf], 0.f);

        for (int ti = 0; ti < nky * nkx; ti++) {
            const int ky = kys[ti / nkx], sy = sys[ti / nkx];
            const int kx = kxs[ti % nkx], sx = sxs[ti % nkx];
            const int tap = ky * 3 + kx;
            for (int sp = 0; sp < 3; sp++) {
                const __nv_bfloat16* Ag = (sp == 2) ? inL : inH;
                const __nv_bfloat16* Bg = ((sp == 1) ? wL : wH) + (size_t)tap * Cout * Cin;
                for (int kc = 0; kc < nkc; kc++) {
                    const int ck0 = kc * 64;
                    __syncthreads();
                    for (int i = tid; i < 1024; i += 256) {
                        int row = i >> 3, e = i & 7;
                        int ii = row >> 5, jj = row & 31;
                        int gy = y0 + ii + sy, gx = x0 + jj + sx;
                        uint4 v = make_uint4(0u, 0u, 0u, 0u);
                        if (gy < Hin && gx < Win)
                            v = *(const uint4*)(Ag + (((size_t)n * Hin + gy) * Win + gx) * Cin + ck0 + e * 8);
                        *(uint4*)((char*)As + row * 144 + e * 16) = v;
                    }
                    for (int i = tid; i < NT * 8; i += 256) {
                        int row = i >> 3, e = i & 7;
                        uint4 v = *(const uint4*)(Bg + (size_t)(och * NT + row) * Cin + ck0 + e * 8);
                        *(uint4*)((char*)Bs + row * 144 + e * 16) = v;
                    }
                    __syncthreads();
#pragma unroll
                    for (int kf = 0; kf < 4; kf++) {
                        wmma::fragment<wmma::matrix_a, 16, 16, 16, __nv_bfloat16, wmma::row_major> af0, af1;
                        wmma::load_matrix_sync(af0, As + (wm * 32) * 72 + kf * 16, 72);
                        wmma::load_matrix_sync(af1, As + (wm * 32 + 16) * 72 + kf * 16, 72);
#pragma unroll
                        for (int nf = 0; nf < NFRAG; nf++) {
                            wmma::fragment<wmma::matrix_b, 16, 16, 16, __nv_bfloat16, wmma::col_major> bfr;
                            wmma::load_matrix_sync(bfr, Bs + (wn * (NT / 2) + nf * 16) * 72 + kf * 16, 72);
                            wmma::mma_sync(acc[0][nf], af0, bfr, acc[0][nf]);
                            wmma::mma_sync(acc[1][nf], af1, bfr, acc[1][nf]);
                        }
                    }
                }
            }
        }
        __syncthreads();
#pragma unroll
        for (int mf = 0; mf < 2; mf++)
#pragma unroll
            for (int nf = 0; nf < NFRAG; nf++)
                wmma::store_matrix_sync(Cs + (wm * 32 + mf * 16) * ldC + wn * (NT / 2) + nf * 16,
                                        acc[mf][nf], ldC, wmma::mem_row_major);
        __syncthreads();
        for (int i = tid; i < 128 * NT; i += 256) {
            int m = i / NT, oc = i % NT;
            int ii = m >> 5, jj = m & 31;
            int oy = 2 * (y0 + ii) + dy, ox = 2 * (x0 + jj) + dx;
            int ocg = och * NT + oc;
            float v = Cs[m * ldC + oc] + bias[ocg];
            v = v > 0.f ? v : 0.f;
            if (OUTF) {
                outF[(((size_t)n * Cout + ocg) * Hout + oy) * Wout + ox] = v;
            } else {
                __nv_bfloat16 h = __float2bfloat16(v);
                float r = v - __bfloat162float(h);
                size_t px = ((size_t)n * Hout + oy) * Wout + ox;
                outH[px * Cout + ocg] = h;
                outL[px * Cout + ocg] = __float2bfloat16(r);
            }
        }
        __syncthreads();
    }
}

// ---------------- host launcher ----------------
extern "C" void kernel_launch(void* const* d_in, const int* in_sizes, int n_in,
                              void* d_out, int out_size)
{
    const float* x  = (const float*)d_in[0];
    const float* w1 = (const float*)d_in[1];  const float* b1 = (const float*)d_in[2];
    const float* w2 = (const float*)d_in[3];  const float* b2 = (const float*)d_in[4];
    const float* w3 = (const float*)d_in[5];  const float* b3 = (const float*)d_in[6];
    const float* w4 = (const float*)d_in[7];  const float* b4 = (const float*)d_in[8];
    const float* cb = (const float*)d_in[9];
    const float* d1w = (const float*)d_in[10]; const float* d1b = (const float*)d_in[11];
    const float* d2w = (const float*)d_in[12]; const float* d2b = (const float*)d_in[13];
    const float* d3w = (const float*)d_in[14]; const float* d3b = (const float*)d_in[15];
    const float* wo = (const float*)d_in[16]; const float* bo = (const float*)d_in[17];
    float* out = (float*)d_out;

    float *h1, *h2, *h3, *z, *zf, *g3, *cn;
    __nv_bfloat16 *zqh, *zql, *g1h, *g1l, *g2h, *g2l;
    __nv_bfloat16 *w1h, *w1l, *w2h, *w2l, *w3h, *w3l;
    cudaGetSymbolAddress((void**)&h1, g_h1);
    cudaGetSymbolAddress((void**)&h2, g_h2);
    cudaGetSymbolAddress((void**)&h3, g_h3);
    cudaGetSymbolAddress((void**)&z,  g_z);
    cudaGetSymbolAddress((void**)&zf, g_zf);
    cudaGetSymbolAddress((void**)&g3, g_g3);
    cudaGetSymbolAddress((void**)&cn, g_cn);
    cudaGetSymbolAddress((void**)&zqh, g_zqh);
    cudaGetSymbolAddress((void**)&zql, g_zql);
    cudaGetSymbolAddress((void**)&g1h, g_g1h);
    cudaGetSymbolAddress((void**)&g1l, g_g1l);
    cudaGetSymbolAddress((void**)&g2h, g_g2h);
    cudaGetSymbolAddress((void**)&g2l, g_g2l);
    cudaGetSymbolAddress((void**)&w1h, g_w1h);
    cudaGetSymbolAddress((void**)&w1l, g_w1l);
    cudaGetSymbolAddress((void**)&w2h, g_w2h);
    cudaGetSymbolAddress((void**)&w2l, g_w2l);
    cudaGetSymbolAddress((void**)&w3h, g_w3h);
    cudaGetSymbolAddress((void**)&w3l, g_w3l);

    // independent prep
    cnorm_k<<<1024, 256>>>(cb, cn);
    wprep_k<<<(9 * 512 * 256 + 255) / 256, 256>>>(d1w, w1h, w1l, 512, 256);
    wprep_k<<<(9 * 256 * 128 + 255) / 256, 256>>>(d2w, w2h, w2l, 256, 128);
    wprep_k<<<(9 * 128 *  64 + 255) / 256, 256>>>(d3w, w3h, w3l, 128, 64);

    // Encoder
    conv8s_k<1, 8, 1><<<dim3( 8, 64, NB), 128>>>(x,  w1, b1, h1,   3,  64, 256, 256, 256, 256);
    conv8s_k<2, 8, 1><<<dim3(16, 16, NB), 128>>>(h1, w2, b2, h2,  64, 128, 256, 256, 128, 128);
    conv8s_k<2, 8, 1><<<dim3(32,  4, NB), 128>>>(h2, w3, b3, h3, 128, 256, 128, 128,  64,  64);
    conv8s_k<2, 8, 0><<<dim3(64,  1, NB), 128>>>(h3, w4, b4, z,  256, 512,  64,  64,  32,  32);

    // Quantize (fused: index tail + bf16 hi/lo channels-last zq)
    zt_k<<<512, 256>>>(z, zf);
    const int qsmem = (32 * ZPQ + 2 * 1024 * CPQ) * 4;  // 230400 B
    cudaFuncSetAttribute(quant8_k, cudaFuncAttributeMaxDynamicSharedMemorySize, qsmem);
    quant8_k<<<512, 512, qsmem>>>(zf, cb, cn, zqh, zql, out,
                                  (long)NB * 3 * 256 * 256, (long)out_size);

    // Decoder: WMMA split-bf16 polyphase GEMMs
    const int sm4 = 128 * 136 * 4;   // 69632
    const int sm2 = 128 * 72 * 4;    // 36864
    cudaFuncSetAttribute((const void*)deconvW_k<4, 0>, cudaFuncAttributeMaxDynamicSharedMemorySize, sm4);
    cudaFuncSetAttribute((const void*)deconvW_k<2, 1>, cudaFuncAttributeMaxDynamicSharedMemorySize, sm2);

    // d1: 32x32 -> 64x64, Cin=512, Cout=256 (nch=2)
    deconvW_k<4, 0><<<NB * 8 * 1 * 2, 256, sm4>>>(zqh, zql, w1h, w1l, d1b,
                                                  g1h, g1l, nullptr,
                                                  512, 256, 32, 32, 8, 1, 2);
    // d2: 64x64 -> 128x128, Cin=256, Cout=128
    deconvW_k<4, 0><<<NB * 16 * 2 * 1, 256, sm4>>>(g1h, g1l, w2h, w2l, d2b,
                                                   g2h, g2l, nullptr,
                                                   256, 128, 64, 64, 16, 2, 1);
    // d3: 128x128 -> 256x256, Cin=128, Cout=64, f32 NCHW out
    deconvW_k<2, 1><<<NB * 32 * 4 * 1, 256, sm2>>>(g2h, g2l, w3h, w3l, d3b,
                                                   nullptr, nullptr, g3,
                                                   128, 64, 128, 128, 32, 4, 1);

    // Final sigmoid conv (scalar)
    conv8s_k<1, 3, 2><<<dim3(1, 64, NB), 128>>>(g3, wo, bo, out, 64, 3, 256, 256, 256, 256);
}

// round 13
// speedup vs baseline: 1.1565x; 1.0423x over previous
#include <cuda_runtime.h>
#include <cuda_bf16.h>
#include <mma.h>
#include <cstdint>
#include <math.h>

using namespace nvcuda;

// ---------------- scratch (device globals; no allocations) ----------------
#define NB 16
__device__ float g_h1[NB*64*256*256];
__device__ float g_h2[NB*128*128*128];
__device__ float g_h3[NB*256*64*64];
__device__ float g_z [NB*512*32*32];
__device__ float g_zf[NB*1024*512];
__device__ float g_g3[NB*64*256*256];
__device__ float g_cn[8192];
__device__ __nv_bfloat16 g_zqh[16384*512];
__device__ __nv_bfloat16 g_zql[16384*512];
__device__ __nv_bfloat16 g_g1h[NB*64*64*256];
__device__ __nv_bfloat16 g_g1l[NB*64*64*256];
__device__ __nv_bfloat16 g_g2h[NB*128*128*128];
__device__ __nv_bfloat16 g_g2l[NB*128*128*128];
__device__ __nv_bfloat16 g_w1h[9*256*512];
__device__ __nv_bfloat16 g_w1l[9*256*512];
__device__ __nv_bfloat16 g_w2h[9*128*256];
__device__ __nv_bfloat16 g_w2l[9*128*256];
__device__ __nv_bfloat16 g_w3h[9*64*128];
__device__ __nv_bfloat16 g_w3l[9*64*128];

// ---------------- 3x3 conv, pad=1, 8-wide, TC output channels ----------------
template<int STRIDE, int TC, int ACT>
__global__ void __launch_bounds__(128) conv8s_k(
    const float* __restrict__ in, const float* __restrict__ wgt,
    const float* __restrict__ bias, float* __restrict__ out,
    int Cin, int Cout, int Hin, int Win, int Hout, int Wout)
{
    constexpr int CICH = 32;
    constexpr int NW = (STRIDE == 1) ? 10 : 17;
    __shared__ float wsf[CICH * TC * 12];

    const int tid  = threadIdx.x;
    const int W8   = Wout >> 3;
    const int rows = 128 / W8;
    const int q    = tid % W8;
    const int oy   = blockIdx.y * rows + tid / W8;
    const int ox0  = q * 8;
    const int ocg  = blockIdx.x * TC;
    const int n    = blockIdx.z;

    float acc[TC][8];
#pragma unroll
    for (int o = 0; o < TC; o++)
#pragma unroll
        for (int j = 0; j < 8; j++) acc[o][j] = 0.f;

    bool rval[3]; int iyo[3];
#pragma unroll
    for (int ky = 0; ky < 3; ky++) {
        int iy = oy * STRIDE + ky - 1;
        rval[ky] = (iy >= 0 && iy < Hin);
        iyo[ky] = iy < 0 ? 0 : (iy >= Hin ? Hin - 1 : iy);
    }

    auto loadRow = [&](float (&w)[NW], int cabs, int ky) {
        const float* rp = in + ((size_t)(n * Cin + cabs) * Hin + iyo[ky]) * Win;
        if (STRIDE == 1) {
            float4 a = *(const float4*)(rp + ox0);
            float4 b = *(const float4*)(rp + ox0 + 4);
            float lft = __shfl_up_sync(0xffffffffu, b.w, 1);
            float rgt = __shfl_down_sync(0xffffffffu, a.x, 1);
            if (q == 0) lft = 0.f;
            if (q == W8 - 1) rgt = 0.f;
            w[0]=lft; w[1]=a.x; w[2]=a.y; w[3]=a.z; w[4]=a.w;
            w[5]=b.x; w[6]=b.y; w[7]=b.z; w[8]=b.w; w[9]=rgt;
        } else {
            const int ib = ox0 * 2;
            float4 a = *(const float4*)(rp + ib);
            float4 b = *(const float4*)(rp + ib + 4);
            float4 c = *(const float4*)(rp + ib + 8);
            float4 d = *(const float4*)(rp + ib + 12);
            float lft = __shfl_up_sync(0xffffffffu, d.w, 1);
            if (q == 0) lft = 0.f;
            w[0]=lft;
            w[1]=a.x; w[2]=a.y; w[3]=a.z; w[4]=a.w;
            w[5]=b.x; w[6]=b.y; w[7]=b.z; w[8]=b.w;
            w[9]=c.x; w[10]=c.y; w[11]=c.z; w[12]=c.w;
            w[13]=d.x; w[14]=d.y; w[15]=d.z; w[16]=d.w;
        }
        if (!rval[ky]) {
#pragma unroll
            for (int i = 0; i < NW; i++) w[i] = 0.f;
        }
    };

    auto computeRow = [&](float (&w)[NW], int ci, int ky) {
#pragma unroll
        for (int oc = 0; oc < TC; oc++) {
            const float4 wv = *(const float4*)(wsf + (ci * TC + oc) * 12 + ky * 4);
#pragma unroll
            for (int j = 0; j < 8; j++) {
                float a = acc[oc][j];
                a = fmaf(w[j * STRIDE + 0], wv.x, a);
                a = fmaf(w[j * STRIDE + 1], wv.y, a);
                a = fmaf(w[j * STRIDE + 2], wv.z, a);
                acc[oc][j] = a;
            }
        }
    };

    float bufA[NW], bufB[NW];
    for (int cc = 0; cc < Cin; cc += CICH) {
        const int chunk = min(CICH, Cin - cc);
        __syncthreads();
        for (int i = tid; i < chunk * TC * 9; i += 128) {
            int ci = i / (TC * 9);
            int r  = i - ci * (TC * 9);
            int oc = r / 9;
            int k  = r - oc * 9;
            wsf[(ci * TC + oc) * 12 + (k / 3) * 4 + (k % 3)] =
                wgt[(size_t)(ocg + oc) * Cin * 9 + (size_t)(cc + ci) * 9 + k];
        }
        __syncthreads();
        const int total = chunk * 3;
        loadRow(bufA, cc, 0);
        for (int m = 0; m < total; m++) {
            const int mn = m + 1;
            if (m & 1) {
                if (mn < total) loadRow(bufA, cc + mn / 3, mn % 3);
                computeRow(bufB, m / 3, m % 3);
            } else {
                if (mn < total) loadRow(bufB, cc + mn / 3, mn % 3);
                computeRow(bufA, m / 3, m % 3);
            }
        }
    }

#pragma unroll
    for (int oc = 0; oc < TC; oc++) {
        float bv = bias[ocg + oc];
        float* op = out + (((size_t)n * Cout + ocg + oc) * Hout + oy) * Wout + ox0;
        float v[8];
#pragma unroll
        for (int j = 0; j < 8; j++) {
            float a = acc[oc][j] + bv;
            if (ACT == 1) a = a > 0.f ? a : 0.f;
            if (ACT == 2) a = 1.f / (1.f + expf(-a));
            v[j] = a;
        }
        *(float4*)(op)     = make_float4(v[0], v[1], v[2], v[3]);
        *(float4*)(op + 4) = make_float4(v[4], v[5], v[6], v[7]);
    }
}

// ---------------- z [B,512,32,32] -> zf [16384, 512] ----------------
__global__ void __launch_bounds__(256) zt_k(const float* __restrict__ z,
                                            float* __restrict__ zf)
{
    __shared__ float t[128 * 33];
    const int blk = blockIdx.x;
    const int bb  = blk >> 5;
    const int y   = blk & 31;
    const int tid = threadIdx.x;
    for (int cc = 0; cc < 512; cc += 128) {
        __syncthreads();
        for (int i = tid; i < 128 * 32; i += 256) {
            int c = i >> 5, x = i & 31;
            t[c * 33 + x] = z[(((size_t)bb * 512 + cc + c) * 32 + y) * 32 + x];
        }
        __syncthreads();
        for (int i = tid; i < 32 * 128; i += 256) {
            int x = i >> 7, c = i & 127;
            zf[((size_t)bb * 1024 + y * 32 + x) * 512 + cc + c] = t[c * 33 + x];
        }
    }
}

// ---------------- codebook row norms ----------------
__global__ void __launch_bounds__(256) cnorm_k(const float* __restrict__ cb,
                                               float* __restrict__ cn)
{
    const int warp = threadIdx.x >> 5, lane = threadIdx.x & 31;
    const int code = blockIdx.x * 8 + warp;
    const float* p = cb + (size_t)code * 512;
    float s = 0.f;
    for (int d = lane; d < 512; d += 32) { float v = p[d]; s = fmaf(v, v, s); }
#pragma unroll
    for (int o = 16; o > 0; o >>= 1) s += __shfl_xor_sync(0xffffffffu, s, o);
    if (lane == 0) cn[code] = s;
}

// ---------------- generic weight split: w [Cin][Cout][3][3] -> hi/lo [tap][oc][ci]
__global__ void __launch_bounds__(256) wprep_k(const float* __restrict__ w,
                                               __nv_bfloat16* __restrict__ bh,
                                               __nv_bfloat16* __restrict__ bl,
                                               int Cin, int Cout)
{
    int i = blockIdx.x * 256 + threadIdx.x;
    if (i >= 9 * Cin * Cout) return;
    int ci  = i % Cin;
    int r   = i / Cin;
    int oc  = r % Cout;
    int tap = r / Cout;
    float v = w[((size_t)ci * Cout + oc) * 9 + tap];
    __nv_bfloat16 h = __float2bfloat16(v);
    float rr = v - __bfloat162float(h);
    bh[((size_t)tap * Cout + oc) * Cin + ci] = h;
    bl[((size_t)tap * Cout + oc) * Cin + ci] = __float2bfloat16(rr);
}

// ---------------- quantizer: R10 core + epilogue writes zq as bf16 hi/lo ------
#define ZPQ 520
#define CPQ 20
__global__ void __launch_bounds__(512) quant8_k(const float* __restrict__ zf,
                                                const float* __restrict__ cb,
                                                const float* __restrict__ cn,
                                                __nv_bfloat16* __restrict__ zqh,
                                                __nv_bfloat16* __restrict__ zql,
                                                float* __restrict__ out,
                                                long out_off, long out_size)
{
    extern __shared__ float sm[];
    float* zs  = sm;
    float* cbt = sm + 32 * ZPQ;
    const int tid = threadIdx.x;
    const int t   = tid & 127;
    const int rg  = tid >> 7;
    const int r0  = blockIdx.x * 32;
    const int bb  = r0 >> 10;
    const int y   = (r0 >> 5) & 31;

    for (int i = tid; i < 32 * 128; i += 512) {
        int r = i >> 7, dq = i & 127;
        float4 v = *(const float4*)(zf + (size_t)(r0 + r) * 512 + dq * 4);
        *(float4*)(zs + r * ZPQ + dq * 4) = v;
    }

    float best[8]; int bi[8];
#pragma unroll
    for (int r = 0; r < 8; r++) { best[r] = 3.4e38f; bi[r] = 0; }

    auto stage = [&](int cbase, int dch, int buf) {
        float* dst = cbt + buf * (1024 * CPQ);
        for (int i = tid; i < 4096; i += 512) {
            int c = i >> 2, dq = i & 3;
            float4 v = *(const float4*)(cb + (size_t)(cbase + c) * 512 + dch * 16 + dq * 4);
            *(float4*)(dst + c * CPQ + dq * 4) = v;
        }
    };

    for (int ct = 0; ct < 8; ct++) {
        const int cbase = ct * 1024;
        float acc[8][8];
#pragma unroll
        for (int rr = 0; rr < 8; rr++)
#pragma unroll
            for (int k = 0; k < 8; k++) acc[rr][k] = 0.f;

        __syncthreads();
        stage(cbase, 0, 0);
        for (int dch = 0; dch < 32; dch++) {
            __syncthreads();
            if (dch + 1 < 32) stage(cbase, dch + 1, (dch + 1) & 1);
            const float* cbuf = cbt + (dch & 1) * (1024 * CPQ);
#pragma unroll
            for (int dq = 0; dq < 4; dq++) {
                float4 zv[8];
#pragma unroll
                for (int rr = 0; rr < 8; rr++)
                    zv[rr] = *(const float4*)(zs + (rg * 8 + rr) * ZPQ + dch * 16 + dq * 4);
#pragma unroll
                for (int k = 0; k < 8; k++) {
                    float4 cv = *(const float4*)(cbuf + (k * 128 + t) * CPQ + dq * 4);
#pragma unroll
                    for (int rr = 0; rr < 8; rr++) {
                        float a = acc[rr][k];
                        a = fmaf(zv[rr].x, cv.x, a);
                        a = fmaf(zv[rr].y, cv.y, a);
                        a = fmaf(zv[rr].z, cv.z, a);
                        a = fmaf(zv[rr].w, cv.w, a);
                        acc[rr][k] = a;
                    }
                }
            }
        }
#pragma unroll
        for (int k = 0; k < 8; k++) {
            int cand = cbase + k * 128 + t;
            float nv = cn[cand];
#pragma unroll
            for (int rr = 0; rr < 8; rr++) {
                float s = nv - 2.f * acc[rr][k];
                if (s < best[rr]) { best[rr] = s; bi[rr] = cand; }
            }
        }
    }

    float* sv = sm;
    int*   si = (int*)(sm + 512);
    int*   ridx = (int*)(sm + 1024);
    for (int rr = 0; rr < 8; rr++) {
        __syncthreads();
        sv[tid] = best[rr]; si[tid] = bi[rr];
        __syncthreads();
        for (int s = 64; s > 0; s >>= 1) {
            if (t < s) {
                float ov = sv[tid + s]; int oi = si[tid + s];
                if (ov < sv[tid] || (ov == sv[tid] && oi < si[tid])) { sv[tid] = ov; si[tid] = oi; }
            }
            __syncthreads();
        }
        if (t == 0) ridx[rg * 8 + rr] = si[tid];
    }
    __syncthreads();

    if (tid < 32) {
        long o = out_off + r0 + tid;
        if (o < out_size) out[o] = (float)ridx[tid];
    }
    for (int i = tid; i < 32 * 512; i += 512) {
        int x = i >> 9, c = i & 511;
        float v = cb[(size_t)ridx[x] * 512 + c];
        __nv_bfloat16 h = __float2bfloat16(v);
        float r = v - __bfloat162float(h);
        size_t px = (size_t)bb * 1024 + y * 32 + x;
        zqh[px * 512 + c] = h;
        zql[px * 512 + c] = __float2bfloat16(r);
    }
}

// ---------------- deconv via WMMA split-bf16 polyphase GEMM (v2) ----------------
// Stage AH/AL/BH/BL once per (tap,kchunk); run the 3 split passes from smem:
// acc += AH*BH + AH*BL + AL*BH.  CTA tile M=128 px, N=NT=NFRAG*32 ocs.
// OUTF=0: bf16 hi/lo channels-last out (relu). OUTF=1: f32 NCHW out (relu).
template<int NFRAG, int OUTF>
__global__ void __launch_bounds__(256) deconvW_k(
    const __nv_bfloat16* __restrict__ inH, const __nv_bfloat16* __restrict__ inL,
    const __nv_bfloat16* __restrict__ wH,  const __nv_bfloat16* __restrict__ wL,
    const float* __restrict__ bias,
    __nv_bfloat16* __restrict__ outH, __nv_bfloat16* __restrict__ outL,
    float* __restrict__ outF,
    int Cin, int Cout, int Hin, int Win, int ytiles, int xtiles, int nch)
{
    constexpr int NT = NFRAG * 32;
    extern __shared__ char smem[];
    // AH @0 (128x72 bf16, 18432B), AL @18432, BH @36864 (NTx72), BL @36864+NT*144
    __nv_bfloat16* AsH = (__nv_bfloat16*)smem;
    __nv_bfloat16* AsL = (__nv_bfloat16*)(smem + 18432);
    __nv_bfloat16* BsH = (__nv_bfloat16*)(smem + 36864);
    __nv_bfloat16* BsL = (__nv_bfloat16*)(smem + 36864 + NT * 144);
    float* Cs = (float*)smem;
    const int ldC = NT + 8;

    const int tid = threadIdx.x, wid = tid >> 5;
    const int wm = wid >> 1, wn = wid & 1;

    int b = blockIdx.x;
    const int och = b % nch; b /= nch;
    const int x0  = (b % xtiles) * 32; b /= xtiles;
    const int y0  = (b % ytiles) * 4;  b /= ytiles;
    const int n   = b;
    const int Hout = Hin * 2, Wout = Win * 2;
    const int nkc = Cin >> 6;

    for (int cls = 0; cls < 4; cls++) {
        const int dy = cls >> 1, dx = cls & 1;
        int kys[2], sys[2], nky, kxs[2], sxs[2], nkx;
        if (dy == 0) { kys[0]=1; sys[0]=0; nky=1; }
        else         { kys[0]=2; sys[0]=0; kys[1]=0; sys[1]=1; nky=2; }
        if (dx == 0) { kxs[0]=1; sxs[0]=0; nkx=1; }
        else         { kxs[0]=2; sxs[0]=0; kxs[1]=0; sxs[1]=1; nkx=2; }

        wmma::fragment<wmma::accumulator, 16, 16, 16, float> acc[2][NFRAG];
#pragma unroll
        for (int mf = 0; mf < 2; mf++)
#pragma unroll
            for (int nf = 0; nf < NFRAG; nf++) wmma::fill_fragment(acc[mf][nf], 0.f);

        for (int ti = 0; ti < nky * nkx; ti++) {
            const int ky = kys[ti / nkx], sy = sys[ti / nkx];
            const int kx = kxs[ti % nkx], sx = sxs[ti % nkx];
            const int tap = ky * 3 + kx;
            const __nv_bfloat16* BgH = wH + (size_t)tap * Cout * Cin;
            const __nv_bfloat16* BgL = wL + (size_t)tap * Cout * Cin;
            for (int kc = 0; kc < nkc; kc++) {
                const int ck0 = kc * 64;
                __syncthreads();
                // stage A hi+lo: 2048 uint4
                for (int i = tid; i < 2048; i += 256) {
                    int half = i >> 10;
                    int r2 = i & 1023;
                    int row = r2 >> 3, e = r2 & 7;
                    int ii = row >> 5, jj = row & 31;
                    int gy = y0 + ii + sy, gx = x0 + jj + sx;
                    uint4 v = make_uint4(0u, 0u, 0u, 0u);
                    const __nv_bfloat16* Ag = half ? inL : inH;
                    if (gy < Hin && gx < Win)
                        v = *(const uint4*)(Ag + (((size_t)n * Hin + gy) * Win + gx) * Cin + ck0 + e * 8);
                    *(uint4*)(smem + half * 18432 + row * 144 + e * 16) = v;
                }
                // stage B hi+lo: NT*16 uint4
                for (int i = tid; i < NT * 16; i += 256) {
                    int half = (i >= NT * 8) ? 1 : 0;
                    int r2 = half ? i - NT * 8 : i;
                    int row = r2 >> 3, e = r2 & 7;
                    const __nv_bfloat16* Bg = half ? BgL : BgH;
                    uint4 v = *(const uint4*)(Bg + (size_t)(och * NT + row) * Cin + ck0 + e * 8);
                    *(uint4*)(smem + 36864 + half * (NT * 144) + row * 144 + e * 16) = v;
                }
                __syncthreads();
#pragma unroll
                for (int kf = 0; kf < 4; kf++) {
                    wmma::fragment<wmma::matrix_a, 16, 16, 16, __nv_bfloat16, wmma::row_major> aH0, aH1, aL0, aL1;
                    wmma::load_matrix_sync(aH0, AsH + (wm * 32) * 72 + kf * 16, 72);
                    wmma::load_matrix_sync(aH1, AsH + (wm * 32 + 16) * 72 + kf * 16, 72);
                    wmma::load_matrix_sync(aL0, AsL + (wm * 32) * 72 + kf * 16, 72);
                    wmma::load_matrix_sync(aL1, AsL + (wm * 32 + 16) * 72 + kf * 16, 72);
#pragma unroll
                    for (int nf = 0; nf < NFRAG; nf++) {
                        wmma::fragment<wmma::matrix_b, 16, 16, 16, __nv_bfloat16, wmma::col_major> bH, bL;
                        wmma::load_matrix_sync(bH, BsH + (wn * (NT / 2) + nf * 16) * 72 + kf * 16, 72);
                        wmma::load_matrix_sync(bL, BsL + (wn * (NT / 2) + nf * 16) * 72 + kf * 16, 72);
                        wmma::mma_sync(acc[0][nf], aH0, bH, acc[0][nf]);
                        wmma::mma_sync(acc[1][nf], aH1, bH, acc[1][nf]);
                        wmma::mma_sync(acc[0][nf], aH0, bL, acc[0][nf]);
                        wmma::mma_sync(acc[1][nf], aH1, bL, acc[1][nf]);
                        wmma::mma_sync(acc[0][nf], aL0, bH, acc[0][nf]);
                        wmma::mma_sync(acc[1][nf], aL1, bH, acc[1][nf]);
                    }
                }
            }
        }
        __syncthreads();
#pragma unroll
        for (int mf = 0; mf < 2; mf++)
#pragma unroll
            for (int nf = 0; nf < NFRAG; nf++)
                wmma::store_matrix_sync(Cs + (wm * 32 + mf * 16) * ldC + wn * (NT / 2) + nf * 16,
                                        acc[mf][nf], ldC, wmma::mem_row_major);
        __syncthreads();
        for (int i = tid; i < 128 * NT; i += 256) {
            int m = i / NT, oc = i % NT;
            int ii = m >> 5, jj = m & 31;
            int oy = 2 * (y0 + ii) + dy, ox = 2 * (x0 + jj) + dx;
            int ocg = och * NT + oc;
            float v = Cs[m * ldC + oc] + bias[ocg];
            v = v > 0.f ? v : 0.f;
            if (OUTF) {
                outF[(((size_t)n * Cout + ocg) * Hout + oy) * Wout + ox] = v;
            } else {
                __nv_bfloat16 h = __float2bfloat16(v);
                float r = v - __bfloat162float(h);
                size_t px = ((size_t)n * Hout + oy) * Wout + ox;
                outH[px * Cout + ocg] = h;
                outL[px * Cout + ocg] = __float2bfloat16(r);
            }
        }
        __syncthreads();
    }
}

// ---------------- host launcher ----------------
extern "C" void kernel_launch(void* const* d_in, const int* in_sizes, int n_in,
                              void* d_out, int out_size)
{
    const float* x  = (const float*)d_in[0];
    const float* w1 = (const float*)d_in[1];  const float* b1 = (const float*)d_in[2];
    const float* w2 = (const float*)d_in[3];  const float* b2 = (const float*)d_in[4];
    const float* w3 = (const float*)d_in[5];  const float* b3 = (const float*)d_in[6];
    const float* w4 = (const float*)d_in[7];  const float* b4 = (const float*)d_in[8];
    const float* cb = (const float*)d_in[9];
    const float* d1w = (const float*)d_in[10]; const float* d1b = (const float*)d_in[11];
    const float* d2w = (const float*)d_in[12]; const float* d2b = (const float*)d_in[13];
    const float* d3w = (const float*)d_in[14]; const float* d3b = (const float*)d_in[15];
    const float* wo = (const float*)d_in[16]; const float* bo = (const float*)d_in[17];
    float* out = (float*)d_out;

    float *h1, *h2, *h3, *z, *zf, *g3, *cn;
    __nv_bfloat16 *zqh, *zql, *g1h, *g1l, *g2h, *g2l;
    __nv_bfloat16 *w1h, *w1l, *w2h, *w2l, *w3h, *w3l;
    cudaGetSymbolAddress((void**)&h1, g_h1);
    cudaGetSymbolAddress((void**)&h2, g_h2);
    cudaGetSymbolAddress((void**)&h3, g_h3);
    cudaGetSymbolAddress((void**)&z,  g_z);
    cudaGetSymbolAddress((void**)&zf, g_zf);
    cudaGetSymbolAddress((void**)&g3, g_g3);
    cudaGetSymbolAddress((void**)&cn, g_cn);
    cudaGetSymbolAddress((void**)&zqh, g_zqh);
    cudaGetSymbolAddress((void**)&zql, g_zql);
    cudaGetSymbolAddress((void**)&g1h, g_g1h);
    cudaGetSymbolAddress((void**)&g1l, g_g1l);
    cudaGetSymbolAddress((void**)&g2h, g_g2h);
    cudaGetSymbolAddress((void**)&g2l, g_g2l);
    cudaGetSymbolAddress((void**)&w1h, g_w1h);
    cudaGetSymbolAddress((void**)&w1l, g_w1l);
    cudaGetSymbolAddress((void**)&w2h, g_w2h);
    cudaGetSymbolAddress((void**)&w2l, g_w2l);
    cudaGetSymbolAddress((void**)&w3h, g_w3h);
    cudaGetSymbolAddress((void**)&w3l, g_w3l);

    // independent prep
    cnorm_k<<<1024, 256>>>(cb, cn);
    wprep_k<<<(9 * 512 * 256 + 255) / 256, 256>>>(d1w, w1h, w1l, 512, 256);
    wprep_k<<<(9 * 256 * 128 + 255) / 256, 256>>>(d2w, w2h, w2l, 256, 128);
    wprep_k<<<(9 * 128 *  64 + 255) / 256, 256>>>(d3w, w3h, w3l, 128, 64);

    // Encoder
    conv8s_k<1, 8, 1><<<dim3( 8, 64, NB), 128>>>(x,  w1, b1, h1,   3,  64, 256, 256, 256, 256);
    conv8s_k<2, 8, 1><<<dim3(16, 16, NB), 128>>>(h1, w2, b2, h2,  64, 128, 256, 256, 128, 128);
    conv8s_k<2, 8, 1><<<dim3(32,  4, NB), 128>>>(h2, w3, b3, h3, 128, 256, 128, 128,  64,  64);
    conv8s_k<2, 8, 0><<<dim3(64,  1, NB), 128>>>(h3, w4, b4, z,  256, 512,  64,  64,  32,  32);

    // Quantize (fused: index tail + bf16 hi/lo channels-last zq)
    zt_k<<<512, 256>>>(z, zf);
    const int qsmem = (32 * ZPQ + 2 * 1024 * CPQ) * 4;  // 230400 B
    cudaFuncSetAttribute(quant8_k, cudaFuncAttributeMaxDynamicSharedMemorySize, qsmem);
    quant8_k<<<512, 512, qsmem>>>(zf, cb, cn, zqh, zql, out,
                                  (long)NB * 3 * 256 * 256, (long)out_size);

    // Decoder: WMMA split-bf16 polyphase GEMMs (4-tile staging, 3 passes from smem)
    const int sm4 = 36864 + 2 * 128 * 144;  // 73728 (Cs 69632 aliases)
    const int sm2 = 36864 + 2 *  64 * 144;  // 55296 (Cs 36864 aliases)
    cudaFuncSetAttribute((const void*)deconvW_k<4, 0>, cudaFuncAttributeMaxDynamicSharedMemorySize, sm4);
    cudaFuncSetAttribute((const void*)deconvW_k<2, 1>, cudaFuncAttributeMaxDynamicSharedMemorySize, sm2);

    // d1: 32x32 -> 64x64, Cin=512, Cout=256 (nch=2)
    deconvW_k<4, 0><<<NB * 8 * 1 * 2, 256, sm4>>>(zqh, zql, w1h, w1l, d1b,
                                                  g1h, g1l, nullptr,
                                                  512, 256, 32, 32, 8, 1, 2);
    // d2: 64x64 -> 128x128, Cin=256, Cout=128
    deconvW_k<4, 0><<<NB * 16 * 2 * 1, 256, sm4>>>(g1h, g1l, w2h, w2l, d2b,
                                                   g2h, g2l, nullptr,
                                                   256, 128, 64, 64, 16, 2, 1);
    // d3: 128x128 -> 256x256, Cin=128, Cout=64, f32 NCHW out
    deconvW_k<2, 1><<<NB * 32 * 4 * 1, 256, sm2>>>(g2h, g2l, w3h, w3l, d3b,
                                                   nullptr, nullptr, g3,
                                                   128, 64, 128, 128, 32, 4, 1);

    // Final sigmoid conv (scalar)
    conv8s_k<1, 3, 2><<<dim3(1, 64, NB), 128>>>(g3, wo, bo, out, 64, 3, 256, 256, 256, 256);
}

// round 14
// speedup vs baseline: 1.5926x; 1.3771x over previous
#include <cuda_runtime.h>
#include <cuda_bf16.h>
#include <mma.h>
#include <cstdint>
#include <math.h>

using namespace nvcuda;

// ---------------- scratch (device globals; no allocations) ----------------
#define NB 16
__device__ float g_h1[NB*64*256*256];
__device__ float g_h2[NB*128*128*128];
__device__ float g_h3[NB*256*64*64];
__device__ float g_z [NB*512*32*32];
__device__ float g_zf[NB*1024*512];
__device__ float g_g3[NB*64*256*256];
__device__ float g_cn[8192];
__device__ float g_sc[(size_t)16384*8192];   // approx scores (512MB)
__device__ unsigned int g_rb[16384];         // per-row encoded min
__device__ int g_idx[16384];
__device__ __nv_bfloat16 g_zfh[16384*512];
__device__ __nv_bfloat16 g_zfl[16384*512];
__device__ __nv_bfloat16 g_cbh[8192*512];
__device__ __nv_bfloat16 g_cbl[8192*512];
__device__ __nv_bfloat16 g_zqh[16384*512];
__device__ __nv_bfloat16 g_zql[16384*512];
__device__ __nv_bfloat16 g_g1h[NB*64*64*256];
__device__ __nv_bfloat16 g_g1l[NB*64*64*256];
__device__ __nv_bfloat16 g_g2h[NB*128*128*128];
__device__ __nv_bfloat16 g_g2l[NB*128*128*128];
__device__ __nv_bfloat16 g_w1h[9*256*512];
__device__ __nv_bfloat16 g_w1l[9*256*512];
__device__ __nv_bfloat16 g_w2h[9*128*256];
__device__ __nv_bfloat16 g_w2l[9*128*256];
__device__ __nv_bfloat16 g_w3h[9*64*128];
__device__ __nv_bfloat16 g_w3l[9*64*128];

__device__ __forceinline__ unsigned int encf(float f) {
    unsigned int u = __float_as_uint(f);
    return (u & 0x80000000u) ? ~u : (u | 0x80000000u);
}
__device__ __forceinline__ float decf(unsigned int u) {
    return (u & 0x80000000u) ? __uint_as_float(u ^ 0x80000000u) : __uint_as_float(~u);
}

// ---------------- 3x3 conv, pad=1, 8-wide, TC output channels ----------------
template<int STRIDE, int TC, int ACT>
__global__ void __launch_bounds__(128) conv8s_k(
    const float* __restrict__ in, const float* __restrict__ wgt,
    const float* __restrict__ bias, float* __restrict__ out,
    int Cin, int Cout, int Hin, int Win, int Hout, int Wout)
{
    constexpr int CICH = 32;
    constexpr int NW = (STRIDE == 1) ? 10 : 17;
    __shared__ float wsf[CICH * TC * 12];

    const int tid  = threadIdx.x;
    const int W8   = Wout >> 3;
    const int rows = 128 / W8;
    const int q    = tid % W8;
    const int oy   = blockIdx.y * rows + tid / W8;
    const int ox0  = q * 8;
    const int ocg  = blockIdx.x * TC;
    const int n    = blockIdx.z;

    float acc[TC][8];
#pragma unroll
    for (int o = 0; o < TC; o++)
#pragma unroll
        for (int j = 0; j < 8; j++) acc[o][j] = 0.f;

    bool rval[3]; int iyo[3];
#pragma unroll
    for (int ky = 0; ky < 3; ky++) {
        int iy = oy * STRIDE + ky - 1;
        rval[ky] = (iy >= 0 && iy < Hin);
        iyo[ky] = iy < 0 ? 0 : (iy >= Hin ? Hin - 1 : iy);
    }

    auto loadRow = [&](float (&w)[NW], int cabs, int ky) {
        const float* rp = in + ((size_t)(n * Cin + cabs) * Hin + iyo[ky]) * Win;
        if (STRIDE == 1) {
            float4 a = *(const float4*)(rp + ox0);
            float4 b = *(const float4*)(rp + ox0 + 4);
            float lft = __shfl_up_sync(0xffffffffu, b.w, 1);
            float rgt = __shfl_down_sync(0xffffffffu, a.x, 1);
            if (q == 0) lft = 0.f;
            if (q == W8 - 1) rgt = 0.f;
            w[0]=lft; w[1]=a.x; w[2]=a.y; w[3]=a.z; w[4]=a.w;
            w[5]=b.x; w[6]=b.y; w[7]=b.z; w[8]=b.w; w[9]=rgt;
        } else {
            const int ib = ox0 * 2;
            float4 a = *(const float4*)(rp + ib);
            float4 b = *(const float4*)(rp + ib + 4);
            float4 c = *(const float4*)(rp + ib + 8);
            float4 d = *(const float4*)(rp + ib + 12);
            float lft = __shfl_up_sync(0xffffffffu, d.w, 1);
            if (q == 0) lft = 0.f;
            w[0]=lft;
            w[1]=a.x; w[2]=a.y; w[3]=a.z; w[4]=a.w;
            w[5]=b.x; w[6]=b.y; w[7]=b.z; w[8]=b.w;
            w[9]=c.x; w[10]=c.y; w[11]=c.z; w[12]=c.w;
            w[13]=d.x; w[14]=d.y; w[15]=d.z; w[16]=d.w;
        }
        if (!rval[ky]) {
#pragma unroll
            for (int i = 0; i < NW; i++) w[i] = 0.f;
        }
    };

    auto computeRow = [&](float (&w)[NW], int ci, int ky) {
#pragma unroll
        for (int oc = 0; oc < TC; oc++) {
            const float4 wv = *(const float4*)(wsf + (ci * TC + oc) * 12 + ky * 4);
#pragma unroll
            for (int j = 0; j < 8; j++) {
                float a = acc[oc][j];
                a = fmaf(w[j * STRIDE + 0], wv.x, a);
                a = fmaf(w[j * STRIDE + 1], wv.y, a);
                a = fmaf(w[j * STRIDE + 2], wv.z, a);
                acc[oc][j] = a;
            }
        }
    };

    float bufA[NW], bufB[NW];
    for (int cc = 0; cc < Cin; cc += CICH) {
        const int chunk = min(CICH, Cin - cc);
        __syncthreads();
        for (int i = tid; i < chunk * TC * 9; i += 128) {
            int ci = i / (TC * 9);
            int r  = i - ci * (TC * 9);
            int oc = r / 9;
            int k  = r - oc * 9;
            wsf[(ci * TC + oc) * 12 + (k / 3) * 4 + (k % 3)] =
                wgt[(size_t)(ocg + oc) * Cin * 9 + (size_t)(cc + ci) * 9 + k];
        }
        __syncthreads();
        const int total = chunk * 3;
        loadRow(bufA, cc, 0);
        for (int m = 0; m < total; m++) {
            const int mn = m + 1;
            if (m & 1) {
                if (mn < total) loadRow(bufA, cc + mn / 3, mn % 3);
                computeRow(bufB, m / 3, m % 3);
            } else {
                if (mn < total) loadRow(bufB, cc + mn / 3, mn % 3);
                computeRow(bufA, m / 3, m % 3);
            }
        }
    }

#pragma unroll
    for (int oc = 0; oc < TC; oc++) {
        float bv = bias[ocg + oc];
        float* op = out + (((size_t)n * Cout + ocg + oc) * Hout + oy) * Wout + ox0;
        float v[8];
#pragma unroll
        for (int j = 0; j < 8; j++) {
            float a = acc[oc][j] + bv;
            if (ACT == 1) a = a > 0.f ? a : 0.f;
            if (ACT == 2) a = 1.f / (1.f + expf(-a));
            v[j] = a;
        }
        *(float4*)(op)     = make_float4(v[0], v[1], v[2], v[3]);
        *(float4*)(op + 4) = make_float4(v[4], v[5], v[6], v[7]);
    }
}

// ------- z [B,512,32,32] -> zf [16384,512] fp32 + bf16 hi/lo splits -------
__global__ void __launch_bounds__(256) zt_k(const float* __restrict__ z,
                                            float* __restrict__ zf,
                                            __nv_bfloat16* __restrict__ zfh,
                                            __nv_bfloat16* __restrict__ zfl)
{
    __shared__ float t[128 * 33];
    const int blk = blockIdx.x;
    const int bb  = blk >> 5;
    const int y   = blk & 31;
    const int tid = threadIdx.x;
    for (int cc = 0; cc < 512; cc += 128) {
        __syncthreads();
        for (int i = tid; i < 128 * 32; i += 256) {
            int c = i >> 5, x = i & 31;
            t[c * 33 + x] = z[(((size_t)bb * 512 + cc + c) * 32 + y) * 32 + x];
        }
        __syncthreads();
        for (int i = tid; i < 32 * 128; i += 256) {
            int x = i >> 7, c = i & 127;
            float v = t[c * 33 + x];
            size_t o = ((size_t)bb * 1024 + y * 32 + x) * 512 + cc + c;
            zf[o] = v;
            __nv_bfloat16 h = __float2bfloat16(v);
            zfh[o] = h;
            zfl[o] = __float2bfloat16(v - __bfloat162float(h));
        }
    }
}

// ---------------- codebook row norms ----------------
__global__ void __launch_bounds__(256) cnorm_k(const float* __restrict__ cb,
                                               float* __restrict__ cn)
{
    const int warp = threadIdx.x >> 5, lane = threadIdx.x & 31;
    const int code = blockIdx.x * 8 + warp;
    const float* p = cb + (size_t)code * 512;
    float s = 0.f;
    for (int d = lane; d < 512; d += 32) { float v = p[d]; s = fmaf(v, v, s); }
#pragma unroll
    for (int o = 16; o > 0; o >>= 1) s += __shfl_xor_sync(0xffffffffu, s, o);
    if (lane == 0) cn[code] = s;
}

// ---------------- codebook bf16 split ----------------
__global__ void __launch_bounds__(256) cbsplit_k(const float* __restrict__ cb,
                                                 __nv_bfloat16* __restrict__ ch,
                                                 __nv_bfloat16* __restrict__ cl)
{
    size_t i = (size_t)blockIdx.x * 256 + threadIdx.x;
    if (i >= (size_t)8192 * 512) return;
    float v = cb[i];
    __nv_bfloat16 h = __float2bfloat16(v);
    ch[i] = h;
    cl[i] = __float2bfloat16(v - __bfloat162float(h));
}

// ---------------- rb init ----------------
__global__ void __launch_bounds__(256) rbinit_k(unsigned int* __restrict__ rb)
{
    int i = blockIdx.x * 256 + threadIdx.x;
    if (i < 16384) rb[i] = 0xFFFFFFFFu;
}

// ---------------- generic weight split: w [Cin][Cout][3][3] -> hi/lo [tap][oc][ci]
__global__ void __launch_bounds__(256) wprep_k(const float* __restrict__ w,
                                               __nv_bfloat16* __restrict__ bh,
                                               __nv_bfloat16* __restrict__ bl,
                                               int Cin, int Cout)
{
    int i = blockIdx.x * 256 + threadIdx.x;
    if (i >= 9 * Cin * Cout) return;
    int ci  = i % Cin;
    int r   = i / Cin;
    int oc  = r % Cout;
    int tap = r / Cout;
    float v = w[((size_t)ci * Cout + oc) * 9 + tap];
    __nv_bfloat16 h = __float2bfloat16(v);
    float rr = v - __bfloat162float(h);
    bh[((size_t)tap * Cout + oc) * Cin + ci] = h;
    bl[((size_t)tap * Cout + oc) * Cin + ci] = __float2bfloat16(rr);
}

// ---------------- quant approx GEMM: scores + per-row mins ----------------
// CTA = 128 rows x 128 codes; split-bf16 3-pass; score = cn[c] - 2*dot.
__global__ void __launch_bounds__(256) qgemm_k(
    const __nv_bfloat16* __restrict__ zfh, const __nv_bfloat16* __restrict__ zfl,
    const __nv_bfloat16* __restrict__ cbh, const __nv_bfloat16* __restrict__ cbl,
    const float* __restrict__ cn,
    float* __restrict__ sc, unsigned int* __restrict__ rb)
{
    extern __shared__ char smem[];
    __nv_bfloat16* AsH = (__nv_bfloat16*)smem;
    __nv_bfloat16* AsL = (__nv_bfloat16*)(smem + 18432);
    __nv_bfloat16* BsH = (__nv_bfloat16*)(smem + 36864);
    __nv_bfloat16* BsL = (__nv_bfloat16*)(smem + 55296);
    float* Cs = (float*)smem;
    const int ldC = 136;

    const int tid = threadIdx.x, wid = tid >> 5, lane = tid & 31;
    const int wm = wid >> 1, wn = wid & 1;
    const int m0 = blockIdx.x * 128;
    const int c0 = blockIdx.y * 128;

    wmma::fragment<wmma::accumulator, 16, 16, 16, float> acc[2][4];
#pragma unroll
    for (int mf = 0; mf < 2; mf++)
#pragma unroll
        for (int nf = 0; nf < 4; nf++) wmma::fill_fragment(acc[mf][nf], 0.f);

    for (int kc = 0; kc < 8; kc++) {
        const int ck0 = kc * 64;
        __syncthreads();
        for (int i = tid; i < 2048; i += 256) {
            int half = i >> 10, r2 = i & 1023;
            int row = r2 >> 3, e = r2 & 7;
            const __nv_bfloat16* Ag = half ? zfl : zfh;
            uint4 v = *(const uint4*)(Ag + (size_t)(m0 + row) * 512 + ck0 + e * 8);
            *(uint4*)(smem + half * 18432 + row * 144 + e * 16) = v;
        }
        for (int i = tid; i < 2048; i += 256) {
            int half = i >> 10, r2 = i & 1023;
            int row = r2 >> 3, e = r2 & 7;
            const __nv_bfloat16* Bg = half ? cbl : cbh;
            uint4 v = *(const uint4*)(Bg + (size_t)(c0 + row) * 512 + ck0 + e * 8);
            *(uint4*)(smem + 36864 + half * 18432 + row * 144 + e * 16) = v;
        }
        __syncthreads();
#pragma unroll
        for (int kf = 0; kf < 4; kf++) {
            wmma::fragment<wmma::matrix_a, 16, 16, 16, __nv_bfloat16, wmma::row_major> aH0, aH1, aL0, aL1;
            wmma::load_matrix_sync(aH0, AsH + (wm * 32) * 72 + kf * 16, 72);
            wmma::load_matrix_sync(aH1, AsH + (wm * 32 + 16) * 72 + kf * 16, 72);
            wmma::load_matrix_sync(aL0, AsL + (wm * 32) * 72 + kf * 16, 72);
            wmma::load_matrix_sync(aL1, AsL + (wm * 32 + 16) * 72 + kf * 16, 72);
#pragma unroll
            for (int nf = 0; nf < 4; nf++) {
                wmma::fragment<wmma::matrix_b, 16, 16, 16, __nv_bfloat16, wmma::col_major> bH, bL;
                wmma::load_matrix_sync(bH, BsH + (wn * 64 + nf * 16) * 72 + kf * 16, 72);
                wmma::load_matrix_sync(bL, BsL + (wn * 64 + nf * 16) * 72 + kf * 16, 72);
                wmma::mma_sync(acc[0][nf], aH0, bH, acc[0][nf]);
                wmma::mma_sync(acc[1][nf], aH1, bH, acc[1][nf]);
                wmma::mma_sync(acc[0][nf], aH0, bL, acc[0][nf]);
                wmma::mma_sync(acc[1][nf], aH1, bL, acc[1][nf]);
                wmma::mma_sync(acc[0][nf], aL0, bH, acc[0][nf]);
                wmma::mma_sync(acc[1][nf], aL1, bH, acc[1][nf]);
            }
        }
    }
    __syncthreads();
#pragma unroll
    for (int mf = 0; mf < 2; mf++)
#pragma unroll
        for (int nf = 0; nf < 4; nf++)
            wmma::store_matrix_sync(Cs + (wm * 32 + mf * 16) * ldC + wn * 64 + nf * 16,
                                    acc[mf][nf], ldC, wmma::mem_row_major);
    __syncthreads();

    // write scores (coalesced over oc)
    for (int i = tid; i < 128 * 128; i += 256) {
        int m = i >> 7, oc = i & 127;
        float s = cn[c0 + oc] - 2.f * Cs[m * ldC + oc];
        sc[(size_t)(m0 + m) * 8192 + c0 + oc] = s;
    }
    // per-row min (warp w handles rows w*16..w*16+15)
    for (int j = 0; j < 16; j++) {
        int row = wid * 16 + j;
        float mv = 3.4e38f;
#pragma unroll
        for (int p = 0; p < 4; p++) {
            int oc = lane + p * 32;
            float s = cn[c0 + oc] - 2.f * Cs[row * ldC + oc];
            mv = fminf(mv, s);
        }
#pragma unroll
        for (int o = 16; o > 0; o >>= 1) mv = fminf(mv, __shfl_xor_sync(0xffffffffu, mv, o));
        if (lane == 0) atomicMin(&rb[m0 + row], encf(mv));
    }
}

// ---------------- exact recheck + argmin over candidates ----------------
__global__ void __launch_bounds__(128) qsel_k(
    const float* __restrict__ sc, const unsigned int* __restrict__ rb,
    const float* __restrict__ cn, const float* __restrict__ zf,
    const float* __restrict__ cb, int* __restrict__ idx,
    float* __restrict__ out, long out_off, long out_size)
{
    __shared__ float sv[128];
    __shared__ int   si[128];
    const int row = blockIdx.x;
    const int tid = threadIdx.x;
    const float best = decf(rb[row]);
    const float thr = best + 0.0625f + 2.5e-4f * fabsf(best);

    float bv = 3.4e38f; int bi = 0x7FFFFFFF;
    const float* zp = zf + (size_t)row * 512;
    for (int c = tid; c < 8192; c += 128) {
        float s = sc[(size_t)row * 8192 + c];
        if (s <= thr) {
            const float* cp = cb + (size_t)c * 512;
            float dot = 0.f;
            for (int d = 0; d < 512; d += 4) {
                float4 zv = *(const float4*)(zp + d);
                float4 cv = *(const float4*)(cp + d);
                dot = fmaf(zv.x, cv.x, dot);
                dot = fmaf(zv.y, cv.y, dot);
                dot = fmaf(zv.z, cv.z, dot);
                dot = fmaf(zv.w, cv.w, dot);
            }
            float dd = cn[c] - 2.f * dot;
            if (dd < bv || (dd == bv && c < bi)) { bv = dd; bi = c; }
        }
    }
    sv[tid] = bv; si[tid] = bi;
    __syncthreads();
    for (int s = 64; s > 0; s >>= 1) {
        if (tid < s) {
            float ov = sv[tid + s]; int oi = si[tid + s];
            if (ov < sv[tid] || (ov == sv[tid] && oi < si[tid])) { sv[tid] = ov; si[tid] = oi; }
        }
        __syncthreads();
    }
    if (tid == 0) {
        idx[row] = si[0];
        long o = out_off + row;
        if (o < out_size) out[o] = (float)si[0];
    }
}

// ---------------- zq emit (bf16 hi/lo channels-last) ----------------
__global__ void __launch_bounds__(256) zqemit_k(const float* __restrict__ cb,
                                                const int* __restrict__ idx,
                                                __nv_bfloat16* __restrict__ zqh,
                                                __nv_bfloat16* __restrict__ zql)
{
    const int r0 = blockIdx.x * 32;
    const int tid = threadIdx.x;
    for (int i = tid; i < 32 * 512; i += 256) {
        int x = i >> 9, c = i & 511;
        float v = cb[(size_t)idx[r0 + x] * 512 + c];
        __nv_bfloat16 h = __float2bfloat16(v);
        float r = v - __bfloat162float(h);
        size_t px = (size_t)r0 + x;
        zqh[px * 512 + c] = h;
        zql[px * 512 + c] = __float2bfloat16(r);
    }
}

// ---------------- deconv via WMMA split-bf16 polyphase GEMM (R13) ----------------
template<int NFRAG, int OUTF>
__global__ void __launch_bounds__(256) deconvW_k(
    const __nv_bfloat16* __restrict__ inH, const __nv_bfloat16* __restrict__ inL,
    const __nv_bfloat16* __restrict__ wH,  const __nv_bfloat16* __restrict__ wL,
    const float* __restrict__ bias,
    __nv_bfloat16* __restrict__ outH, __nv_bfloat16* __restrict__ outL,
    float* __restrict__ outF,
    int Cin, int Cout, int Hin, int Win, int ytiles, int xtiles, int nch)
{
    constexpr int NT = NFRAG * 32;
    extern __shared__ char smem[];
    __nv_bfloat16* AsH = (__nv_bfloat16*)smem;
    __nv_bfloat16* AsL = (__nv_bfloat16*)(smem + 18432);
    __nv_bfloat16* BsH = (__nv_bfloat16*)(smem + 36864);
    __nv_bfloat16* BsL = (__nv_bfloat16*)(smem + 36864 + NT * 144);
    float* Cs = (float*)smem;
    const int ldC = NT + 8;

    const int tid = threadIdx.x, wid = tid >> 5;
    const int wm = wid >> 1, wn = wid & 1;

    int b = blockIdx.x;
    const int och = b % nch; b /= nch;
    const int x0  = (b % xtiles) * 32; b /= xtiles;
    const int y0  = (b % ytiles) * 4;  b /= ytiles;
    const int n   = b;
    const int Hout = Hin * 2, Wout = Win * 2;
    const int nkc = Cin >> 6;

    for (int cls = 0; cls < 4; cls++) {
        const int dy = cls >> 1, dx = cls & 1;
        int kys[2], sys[2], nky, kxs[2], sxs[2], nkx;
        if (dy == 0) { kys[0]=1; sys[0]=0; nky=1; }
        else         { kys[0]=2; sys[0]=0; kys[1]=0; sys[1]=1; nky=2; }
        if (dx == 0) { kxs[0]=1; sxs[0]=0; nkx=1; }
        else         { kxs[0]=2; sxs[0]=0; kxs[1]=0; sxs[1]=1; nkx=2; }

        wmma::fragment<wmma::accumulator, 16, 16, 16, float> acc[2][NFRAG];
#pragma unroll
        for (int mf = 0; mf < 2; mf++)
#pragma unroll
            for (int nf = 0; nf < NFRAG; nf++) wmma::fill_fragment(acc[mf][nf], 0.f);

        for (int ti = 0; ti < nky * nkx; ti++) {
            const int ky = kys[ti / nkx], sy = sys[ti / nkx];
            const int kx = kxs[ti % nkx], sx = sxs[ti % nkx];
            const int tap = ky * 3 + kx;
            const __nv_bfloat16* BgH = wH + (size_t)tap * Cout * Cin;
            const __nv_bfloat16* BgL = wL + (size_t)tap * Cout * Cin;
            for (int kc = 0; kc < nkc; kc++) {
                const int ck0 = kc * 64;
                __syncthreads();
                for (int i = tid; i < 2048; i += 256) {
                    int half = i >> 10;
                    int r2 = i & 1023;
                    int row = r2 >> 3, e = r2 & 7;
                    int ii = row >> 5, jj = row & 31;
                    int gy = y0 + ii + sy, gx = x0 + jj + sx;
                    uint4 v = make_uint4(0u, 0u, 0u, 0u);
                    const __nv_bfloat16* Ag = half ? inL : inH;
                    if (gy < Hin && gx < Win)
                        v = *(const uint4*)(Ag + (((size_t)n * Hin + gy) * Win + gx) * Cin + ck0 + e * 8);
                    *(uint4*)(smem + half * 18432 + row * 144 + e * 16) = v;
                }
                for (int i = tid; i < NT * 16; i += 256) {
                    int half = (i >= NT * 8) ? 1 : 0;
                    int r2 = half ? i - NT * 8 : i;
                    int row = r2 >> 3, e = r2 & 7;
                    const __nv_bfloat16* Bg = half ? BgL : BgH;
                    uint4 v = *(const uint4*)(Bg + (size_t)(och * NT + row) * Cin + ck0 + e * 8);
                    *(uint4*)(smem + 36864 + half * (NT * 144) + row * 144 + e * 16) = v;
                }
                __syncthreads();
#pragma unroll
                for (int kf = 0; kf < 4; kf++) {
                    wmma::fragment<wmma::matrix_a, 16, 16, 16, __nv_bfloat16, wmma::row_major> aH0, aH1, aL0, aL1;
                    wmma::load_matrix_sync(aH0, AsH + (wm * 32) * 72 + kf * 16, 72);
                    wmma::load_matrix_sync(aH1, AsH + (wm * 32 + 16) * 72 + kf * 16, 72);
                    wmma::load_matrix_sync(aL0, AsL + (wm * 32) * 72 + kf * 16, 72);
                    wmma::load_matrix_sync(aL1, AsL + (wm * 32 + 16) * 72 + kf * 16, 72);
#pragma unroll
                    for (int nf = 0; nf < NFRAG; nf++) {
                        wmma::fragment<wmma::matrix_b, 16, 16, 16, __nv_bfloat16, wmma::col_major> bH, bL;
                        wmma::load_matrix_sync(bH, BsH + (wn * (NT / 2) + nf * 16) * 72 + kf * 16, 72);
                        wmma::load_matrix_sync(bL, BsL + (wn * (NT / 2) + nf * 16) * 72 + kf * 16, 72);
                        wmma::mma_sync(acc[0][nf], aH0, bH, acc[0][nf]);
                        wmma::mma_sync(acc[1][nf], aH1, bH, acc[1][nf]);
                        wmma::mma_sync(acc[0][nf], aH0, bL, acc[0][nf]);
                        wmma::mma_sync(acc[1][nf], aH1, bL, acc[1][nf]);
                        wmma::mma_sync(acc[0][nf], aL0, bH, acc[0][nf]);
                        wmma::mma_sync(acc[1][nf], aL1, bH, acc[1][nf]);
                    }
                }
            }
        }
        __syncthreads();
#pragma unroll
        for (int mf = 0; mf < 2; mf++)
#pragma unroll
            for (int nf = 0; nf < NFRAG; nf++)
                wmma::store_matrix_sync(Cs + (wm * 32 + mf * 16) * ldC + wn * (NT / 2) + nf * 16,
                                        acc[mf][nf], ldC, wmma::mem_row_major);
        __syncthreads();
        for (int i = tid; i < 128 * NT; i += 256) {
            int m = i / NT, oc = i % NT;
            int ii = m >> 5, jj = m & 31;
            int oy = 2 * (y0 + ii) + dy, ox = 2 * (x0 + jj) + dx;
            int ocg = och * NT + oc;
            float v = Cs[m * ldC + oc] + bias[ocg];
            v = v > 0.f ? v : 0.f;
            if (OUTF) {
                outF[(((size_t)n * Cout + ocg) * Hout + oy) * Wout + ox] = v;
            } else {
                __nv_bfloat16 h = __float2bfloat16(v);
                float r = v - __bfloat162float(h);
                size_t px = ((size_t)n * Hout + oy) * Wout + ox;
                outH[px * Cout + ocg] = h;
                outL[px * Cout + ocg] = __float2bfloat16(r);
            }
        }
        __syncthreads();
    }
}

// ---------------- host launcher ----------------
extern "C" void kernel_launch(void* const* d_in, const int* in_sizes, int n_in,
                              void* d_out, int out_size)
{
    const float* x  = (const float*)d_in[0];
    const float* w1 = (const float*)d_in[1];  const float* b1 = (const float*)d_in[2];
    const float* w2 = (const float*)d_in[3];  const float* b2 = (const float*)d_in[4];
    const float* w3 = (const float*)d_in[5];  const float* b3 = (const float*)d_in[6];
    const float* w4 = (const float*)d_in[7];  const float* b4 = (const float*)d_in[8];
    const float* cb = (const float*)d_in[9];
    const float* d1w = (const float*)d_in[10]; const float* d1b = (const float*)d_in[11];
    const float* d2w = (const float*)d_in[12]; const float* d2b = (const float*)d_in[13];
    const float* d3w = (const float*)d_in[14]; const float* d3b = (const float*)d_in[15];
    const float* wo = (const float*)d_in[16]; const float* bo = (const float*)d_in[17];
    float* out = (float*)d_out;

    float *h1, *h2, *h3, *z, *zf, *g3, *cn, *sc;
    unsigned int* rb;
    int* idx;
    __nv_bfloat16 *zfh, *zfl, *cbh, *cbl, *zqh, *zql, *g1h, *g1l, *g2h, *g2l;
    __nv_bfloat16 *w1h, *w1l, *w2h, *w2l, *w3h, *w3l;
    cudaGetSymbolAddress((void**)&h1, g_h1);
    cudaGetSymbolAddress((void**)&h2, g_h2);
    cudaGetSymbolAddress((void**)&h3, g_h3);
    cudaGetSymbolAddress((void**)&z,  g_z);
    cudaGetSymbolAddress((void**)&zf, g_zf);
    cudaGetSymbolAddress((void**)&g3, g_g3);
    cudaGetSymbolAddress((void**)&cn, g_cn);
    cudaGetSymbolAddress((void**)&sc, g_sc);
    cudaGetSymbolAddress((void**)&rb, g_rb);
    cudaGetSymbolAddress((void**)&idx, g_idx);
    cudaGetSymbolAddress((void**)&zfh, g_zfh);
    cudaGetSymbolAddress((void**)&zfl, g_zfl);
    cudaGetSymbolAddress((void**)&cbh, g_cbh);
    cudaGetSymbolAddress((void**)&cbl, g_cbl);
    cudaGetSymbolAddress((void**)&zqh, g_zqh);
    cudaGetSymbolAddress((void**)&zql, g_zql);
    cudaGetSymbolAddress((void**)&g1h, g_g1h);
    cudaGetSymbolAddress((void**)&g1l, g_g1l);
    cudaGetSymbolAddress((void**)&g2h, g_g2h);
    cudaGetSymbolAddress((void**)&g2l, g_g2l);
    cudaGetSymbolAddress((void**)&w1h, g_w1h);
    cudaGetSymbolAddress((void**)&w1l, g_w1l);
    cudaGetSymbolAddress((void**)&w2h, g_w2h);
    cudaGetSymbolAddress((void**)&w2l, g_w2l);
    cudaGetSymbolAddress((void**)&w3h, g_w3h);
    cudaGetSymbolAddress((void**)&w3l, g_w3l);

    // independent prep
    cnorm_k<<<1024, 256>>>(cb, cn);
    cbsplit_k<<<(8192 * 512 + 255) / 256, 256>>>(cb, cbh, cbl);
    rbinit_k<<<64, 256>>>(rb);
    wprep_k<<<(9 * 512 * 256 + 255) / 256, 256>>>(d1w, w1h, w1l, 512, 256);
    wprep_k<<<(9 * 256 * 128 + 255) / 256, 256>>>(d2w, w2h, w2l, 256, 128);
    wprep_k<<<(9 * 128 *  64 + 255) / 256, 256>>>(d3w, w3h, w3l, 128, 64);

    // Encoder (exact fp32)
    conv8s_k<1, 8, 1><<<dim3( 8, 64, NB), 128>>>(x,  w1, b1, h1,   3,  64, 256, 256, 256, 256);
    conv8s_k<2, 8, 1><<<dim3(16, 16, NB), 128>>>(h1, w2, b2, h2,  64, 128, 256, 256, 128, 128);
    conv8s_k<2, 8, 1><<<dim3(32,  4, NB), 128>>>(h2, w3, b3, h3, 128, 256, 128, 128,  64,  64);
    conv8s_k<2, 8, 0><<<dim3(64,  1, NB), 128>>>(h3, w4, b4, z,  256, 512,  64,  64,  32,  32);

    // Quantize: approx tensor-core scores + exact fp32 recheck
    zt_k<<<512, 256>>>(z, zf, zfh, zfl);
    cudaFuncSetAttribute(qgemm_k, cudaFuncAttributeMaxDynamicSharedMemorySize, 73728);
    qgemm_k<<<dim3(128, 64), 256, 73728>>>(zfh, zfl, cbh, cbl, cn, sc, rb);
    qsel_k<<<16384, 128>>>(sc, rb, cn, zf, cb, idx, out,
                           (long)NB * 3 * 256 * 256, (long)out_size);
    zqemit_k<<<512, 256>>>(cb, idx, zqh, zql);

    // Decoder: WMMA split-bf16 polyphase GEMMs
    const int sm4 = 36864 + 2 * 128 * 144;
    const int sm2 = 36864 + 2 *  64 * 144;
    cudaFuncSetAttribute((const void*)deconvW_k<4, 0>, cudaFuncAttributeMaxDynamicSharedMemorySize, sm4);
    cudaFuncSetAttribute((const void*)deconvW_k<2, 1>, cudaFuncAttributeMaxDynamicSharedMemorySize, sm2);

    deconvW_k<4, 0><<<NB * 8 * 1 * 2, 256, sm4>>>(zqh, zql, w1h, w1l, d1b,
                                                  g1h, g1l, nullptr,
                                                  512, 256, 32, 32, 8, 1, 2);
    deconvW_k<4, 0><<<NB * 16 * 2 * 1, 256, sm4>>>(g1h, g1l, w2h, w2l, d2b,
                                                   g2h, g2l, nullptr,
                                                   256, 128, 64, 64, 16, 2, 1);
    deconvW_k<2, 1><<<NB * 32 * 4 * 1, 256, sm2>>>(g2h, g2l, w3h, w3l, d3b,
                                                   nullptr, nullptr, g3,
                                                   128, 64, 128, 128, 32, 4, 1);

    // Final sigmoid conv (scalar)
    conv8s_k<1, 3, 2><<<dim3(1, 64, NB), 128>>>(g3, wo, bo, out, 64, 3, 256, 256, 256, 256);
}

// round 15
// speedup vs baseline: 1.7413x; 1.0934x over previous
#include <cuda_runtime.h>
#include <cuda_bf16.h>
#include <mma.h>
#include <cstdint>
#include <math.h>

using namespace nvcuda;

// ---------------- scratch (device globals; no allocations) ----------------
#define NB 16
__device__ float g_h1[NB*64*256*256];
__device__ float g_h2[NB*128*128*128];
__device__ float g_h3[NB*256*64*64];
__device__ float g_z [NB*512*32*32];
__device__ float g_zf[NB*1024*512];
__device__ float g_g3[NB*64*256*256];
__device__ float g_cn[8192];
__device__ float g_zn[16384];
__device__ float g_cmax[1];
__device__ float g_sc[(size_t)16384*8192];   // approx scores (512MB)
__device__ unsigned int g_rb[16384];         // per-row encoded min
__device__ int g_idx[16384];
__device__ __nv_bfloat16 g_zfh[16384*512];
__device__ __nv_bfloat16 g_cbh[8192*512];
__device__ __nv_bfloat16 g_zqh[16384*512];
__device__ __nv_bfloat16 g_zql[16384*512];
__device__ __nv_bfloat16 g_g1h[NB*64*64*256];
__device__ __nv_bfloat16 g_g1l[NB*64*64*256];
__device__ __nv_bfloat16 g_g2h[NB*128*128*128];
__device__ __nv_bfloat16 g_g2l[NB*128*128*128];
__device__ __nv_bfloat16 g_w1h[9*256*512];
__device__ __nv_bfloat16 g_w1l[9*256*512];
__device__ __nv_bfloat16 g_w2h[9*128*256];
__device__ __nv_bfloat16 g_w2l[9*128*256];
__device__ __nv_bfloat16 g_w3h[9*64*128];
__device__ __nv_bfloat16 g_w3l[9*64*128];

__device__ __forceinline__ unsigned int encf(float f) {
    unsigned int u = __float_as_uint(f);
    return (u & 0x80000000u) ? ~u : (u | 0x80000000u);
}
__device__ __forceinline__ float decf(unsigned int u) {
    return (u & 0x80000000u) ? __uint_as_float(u ^ 0x80000000u) : __uint_as_float(~u);
}

// ---------------- 3x3 conv, pad=1, 8-wide, TC output channels ----------------
template<int STRIDE, int TC, int ACT>
__global__ void __launch_bounds__(128) conv8s_k(
    const float* __restrict__ in, const float* __restrict__ wgt,
    const float* __restrict__ bias, float* __restrict__ out,
    int Cin, int Cout, int Hin, int Win, int Hout, int Wout)
{
    constexpr int CICH = 32;
    constexpr int NW = (STRIDE == 1) ? 10 : 17;
    __shared__ float wsf[CICH * TC * 12];

    const int tid  = threadIdx.x;
    const int W8   = Wout >> 3;
    const int rows = 128 / W8;
    const int q    = tid % W8;
    const int oy   = blockIdx.y * rows + tid / W8;
    const int ox0  = q * 8;
    const int ocg  = blockIdx.x * TC;
    const int n    = blockIdx.z;

    float acc[TC][8];
#pragma unroll
    for (int o = 0; o < TC; o++)
#pragma unroll
        for (int j = 0; j < 8; j++) acc[o][j] = 0.f;

    bool rval[3]; int iyo[3];
#pragma unroll
    for (int ky = 0; ky < 3; ky++) {
        int iy = oy * STRIDE + ky - 1;
        rval[ky] = (iy >= 0 && iy < Hin);
        iyo[ky] = iy < 0 ? 0 : (iy >= Hin ? Hin - 1 : iy);
    }

    auto loadRow = [&](float (&w)[NW], int cabs, int ky) {
        const float* rp = in + ((size_t)(n * Cin + cabs) * Hin + iyo[ky]) * Win;
        if (STRIDE == 1) {
            float4 a = *(const float4*)(rp + ox0);
            float4 b = *(const float4*)(rp + ox0 + 4);
            float lft = __shfl_up_sync(0xffffffffu, b.w, 1);
            float rgt = __shfl_down_sync(0xffffffffu, a.x, 1);
            if (q == 0) lft = 0.f;
            if (q == W8 - 1) rgt = 0.f;
            w[0]=lft; w[1]=a.x; w[2]=a.y; w[3]=a.z; w[4]=a.w;
            w[5]=b.x; w[6]=b.y; w[7]=b.z; w[8]=b.w; w[9]=rgt;
        } else {
            const int ib = ox0 * 2;
            float4 a = *(const float4*)(rp + ib);
            float4 b = *(const float4*)(rp + ib + 4);
            float4 c = *(const float4*)(rp + ib + 8);
            float4 d = *(const float4*)(rp + ib + 12);
            float lft = __shfl_up_sync(0xffffffffu, d.w, 1);
            if (q == 0) lft = 0.f;
            w[0]=lft;
            w[1]=a.x; w[2]=a.y; w[3]=a.z; w[4]=a.w;
            w[5]=b.x; w[6]=b.y; w[7]=b.z; w[8]=b.w;
            w[9]=c.x; w[10]=c.y; w[11]=c.z; w[12]=c.w;
            w[13]=d.x; w[14]=d.y; w[15]=d.z; w[16]=d.w;
        }
        if (!rval[ky]) {
#pragma unroll
            for (int i = 0; i < NW; i++) w[i] = 0.f;
        }
    };

    auto computeRow = [&](float (&w)[NW], int ci, int ky) {
#pragma unroll
        for (int oc = 0; oc < TC; oc++) {
            const float4 wv = *(const float4*)(wsf + (ci * TC + oc) * 12 + ky * 4);
#pragma unroll
            for (int j = 0; j < 8; j++) {
                float a = acc[oc][j];
                a = fmaf(w[j * STRIDE + 0], wv.x, a);
                a = fmaf(w[j * STRIDE + 1], wv.y, a);
                a = fmaf(w[j * STRIDE + 2], wv.z, a);
                acc[oc][j] = a;
            }
        }
    };

    float bufA[NW], bufB[NW];
    for (int cc = 0; cc < Cin; cc += CICH) {
        const int chunk = min(CICH, Cin - cc);
        __syncthreads();
        for (int i = tid; i < chunk * TC * 9; i += 128) {
            int ci = i / (TC * 9);
            int r  = i - ci * (TC * 9);
            int oc = r / 9;
            int k  = r - oc * 9;
            wsf[(ci * TC + oc) * 12 + (k / 3) * 4 + (k % 3)] =
                wgt[(size_t)(ocg + oc) * Cin * 9 + (size_t)(cc + ci) * 9 + k];
        }
        __syncthreads();
        const int total = chunk * 3;
        loadRow(bufA, cc, 0);
        for (int m = 0; m < total; m++) {
            const int mn = m + 1;
            if (m & 1) {
                if (mn < total) loadRow(bufA, cc + mn / 3, mn % 3);
                computeRow(bufB, m / 3, m % 3);
            } else {
                if (mn < total) loadRow(bufB, cc + mn / 3, mn % 3);
                computeRow(bufA, m / 3, m % 3);
            }
        }
    }

#pragma unroll
    for (int oc = 0; oc < TC; oc++) {
        float bv = bias[ocg + oc];
        float* op = out + (((size_t)n * Cout + ocg + oc) * Hout + oy) * Wout + ox0;
        float v[8];
#pragma unroll
        for (int j = 0; j < 8; j++) {
            float a = acc[oc][j] + bv;
            if (ACT == 1) a = a > 0.f ? a : 0.f;
            if (ACT == 2) a = 1.f / (1.f + expf(-a));
            v[j] = a;
        }
        *(float4*)(op)     = make_float4(v[0], v[1], v[2], v[3]);
        *(float4*)(op + 4) = make_float4(v[4], v[5], v[6], v[7]);
    }
}

// ------- z [B,512,32,32] -> zf [16384,512] fp32 + bf16 hi + row norms -------
__global__ void __launch_bounds__(256) zt_k(const float* __restrict__ z,
                                            float* __restrict__ zf,
                                            __nv_bfloat16* __restrict__ zfh,
                                            float* __restrict__ zn)
{
    __shared__ float t[128 * 33];
    const int blk = blockIdx.x;
    const int bb  = blk >> 5;
    const int y   = blk & 31;
    const int tid = threadIdx.x;
    float nacc = 0.f;
    for (int cc = 0; cc < 512; cc += 128) {
        __syncthreads();
        for (int i = tid; i < 128 * 32; i += 256) {
            int c = i >> 5, x = i & 31;
            t[c * 33 + x] = z[(((size_t)bb * 512 + cc + c) * 32 + y) * 32 + x];
        }
        __syncthreads();
        for (int i = tid; i < 32 * 128; i += 256) {
            int x = i >> 7, c = i & 127;
            float v = t[c * 33 + x];
            size_t o = ((size_t)bb * 1024 + y * 32 + x) * 512 + cc + c;
            zf[o] = v;
            zfh[o] = __float2bfloat16(v);
        }
        if (tid < 32) {
            for (int c = 0; c < 128; c++) {
                float v = t[c * 33 + tid];
                nacc = fmaf(v, v, nacc);
            }
        }
    }
    if (tid < 32) zn[bb * 1024 + y * 32 + tid] = sqrtf(nacc);
}

// ---------------- codebook row norms ----------------
__global__ void __launch_bounds__(256) cnorm_k(const float* __restrict__ cb,
                                               float* __restrict__ cn)
{
    const int warp = threadIdx.x >> 5, lane = threadIdx.x & 31;
    const int code = blockIdx.x * 8 + warp;
    const float* p = cb + (size_t)code * 512;
    float s = 0.f;
    for (int d = lane; d < 512; d += 32) { float v = p[d]; s = fmaf(v, v, s); }
#pragma unroll
    for (int o = 16; o > 0; o >>= 1) s += __shfl_xor_sync(0xffffffffu, s, o);
    if (lane == 0) cn[code] = s;
}

// ---------------- max codebook norm ----------------
__global__ void __launch_bounds__(256) cmax_k(const float* __restrict__ cn,
                                              float* __restrict__ cm)
{
    __shared__ float s[256];
    const int tid = threadIdx.x;
    float m = 0.f;
    for (int i = tid; i < 8192; i += 256) m = fmaxf(m, cn[i]);
    s[tid] = m;
    __syncthreads();
    for (int o = 128; o > 0; o >>= 1) {
        if (tid < o) s[tid] = fmaxf(s[tid], s[tid + o]);
        __syncthreads();
    }
    if (tid == 0) cm[0] = sqrtf(s[0]);
}

// ---------------- codebook bf16 (hi only) ----------------
__global__ void __launch_bounds__(256) cbsplit_k(const float* __restrict__ cb,
                                                 __nv_bfloat16* __restrict__ ch)
{
    size_t i = (size_t)blockIdx.x * 256 + threadIdx.x;
    if (i >= (size_t)8192 * 512) return;
    ch[i] = __float2bfloat16(cb[i]);
}

// ---------------- rb init ----------------
__global__ void __launch_bounds__(256) rbinit_k(unsigned int* __restrict__ rb)
{
    int i = blockIdx.x * 256 + threadIdx.x;
    if (i < 16384) rb[i] = 0xFFFFFFFFu;
}

// ---------------- generic weight split: w [Cin][Cout][3][3] -> hi/lo [tap][oc][ci]
__global__ void __launch_bounds__(256) wprep_k(const float* __restrict__ w,
                                               __nv_bfloat16* __restrict__ bh,
                                               __nv_bfloat16* __restrict__ bl,
                                               int Cin, int Cout)
{
    int i = blockIdx.x * 256 + threadIdx.x;
    if (i >= 9 * Cin * Cout) return;
    int ci  = i % Cin;
    int r   = i / Cin;
    int oc  = r % Cout;
    int tap = r / Cout;
    float v = w[((size_t)ci * Cout + oc) * 9 + tap];
    __nv_bfloat16 h = __float2bfloat16(v);
    float rr = v - __bfloat162float(h);
    bh[((size_t)tap * Cout + oc) * Cin + ci] = h;
    bl[((size_t)tap * Cout + oc) * Cin + ci] = __float2bfloat16(rr);
}

// ---------------- quant approx GEMM (1-pass bf16): scores + per-row mins ------
__global__ void __launch_bounds__(256) qgemm_k(
    const __nv_bfloat16* __restrict__ zfh,
    const __nv_bfloat16* __restrict__ cbh,
    const float* __restrict__ cn,
    float* __restrict__ sc, unsigned int* __restrict__ rb)
{
    extern __shared__ char smem[];
    __nv_bfloat16* As = (__nv_bfloat16*)smem;             // 128x72 pitch144
    __nv_bfloat16* Bs = (__nv_bfloat16*)(smem + 18432);   // 128x72
    float* Cs = (float*)smem;
    const int ldC = 136;

    const int tid = threadIdx.x, wid = tid >> 5, lane = tid & 31;
    const int wm = wid >> 1, wn = wid & 1;
    const int m0 = blockIdx.x * 128;
    const int c0 = blockIdx.y * 128;

    wmma::fragment<wmma::accumulator, 16, 16, 16, float> acc[2][4];
#pragma unroll
    for (int mf = 0; mf < 2; mf++)
#pragma unroll
        for (int nf = 0; nf < 4; nf++) wmma::fill_fragment(acc[mf][nf], 0.f);

    for (int kc = 0; kc < 8; kc++) {
        const int ck0 = kc * 64;
        __syncthreads();
        for (int i = tid; i < 1024; i += 256) {
            int row = i >> 3, e = i & 7;
            uint4 v = *(const uint4*)(zfh + (size_t)(m0 + row) * 512 + ck0 + e * 8);
            *(uint4*)(smem + row * 144 + e * 16) = v;
        }
        for (int i = tid; i < 1024; i += 256) {
            int row = i >> 3, e = i & 7;
            uint4 v = *(const uint4*)(cbh + (size_t)(c0 + row) * 512 + ck0 + e * 8);
            *(uint4*)(smem + 18432 + row * 144 + e * 16) = v;
        }
        __syncthreads();
#pragma unroll
        for (int kf = 0; kf < 4; kf++) {
            wmma::fragment<wmma::matrix_a, 16, 16, 16, __nv_bfloat16, wmma::row_major> a0, a1;
            wmma::load_matrix_sync(a0, As + (wm * 32) * 72 + kf * 16, 72);
            wmma::load_matrix_sync(a1, As + (wm * 32 + 16) * 72 + kf * 16, 72);
#pragma unroll
            for (int nf = 0; nf < 4; nf++) {
                wmma::fragment<wmma::matrix_b, 16, 16, 16, __nv_bfloat16, wmma::col_major> bfr;
                wmma::load_matrix_sync(bfr, Bs + (wn * 64 + nf * 16) * 72 + kf * 16, 72);
                wmma::mma_sync(acc[0][nf], a0, bfr, acc[0][nf]);
                wmma::mma_sync(acc[1][nf], a1, bfr, acc[1][nf]);
            }
        }
    }
    __syncthreads();
#pragma unroll
    for (int mf = 0; mf < 2; mf++)
#pragma unroll
        for (int nf = 0; nf < 4; nf++)
            wmma::store_matrix_sync(Cs + (wm * 32 + mf * 16) * ldC + wn * 64 + nf * 16,
                                    acc[mf][nf], ldC, wmma::mem_row_major);
    __syncthreads();

    for (int i = tid; i < 128 * 128; i += 256) {
        int m = i >> 7, oc = i & 127;
        float s = cn[c0 + oc] - 2.f * Cs[m * ldC + oc];
        sc[(size_t)(m0 + m) * 8192 + c0 + oc] = s;
    }
    for (int j = 0; j < 16; j++) {
        int row = wid * 16 + j;
        float mv = 3.4e38f;
#pragma unroll
        for (int p = 0; p < 4; p++) {
            int oc = lane + p * 32;
            float s = cn[c0 + oc] - 2.f * Cs[row * ldC + oc];
            mv = fminf(mv, s);
        }
#pragma unroll
        for (int o = 16; o > 0; o >>= 1) mv = fminf(mv, __shfl_xor_sync(0xffffffffu, mv, o));
        if (lane == 0) atomicMin(&rb[m0 + row], encf(mv));
    }
}

// ---------------- exact recheck + argmin over candidates ----------------
// thr = 2 * score_error_bound; score_error <= 2*2^-8*(|zh|+|z|)|c|max <= 0.0158*|z|*cmax
__global__ void __launch_bounds__(128) qsel_k(
    const float* __restrict__ sc, const unsigned int* __restrict__ rb,
    const float* __restrict__ cn, const float* __restrict__ zf,
    const float* __restrict__ cb, const float* __restrict__ zn,
    const float* __restrict__ cmax, int* __restrict__ idx,
    float* __restrict__ out, long out_off, long out_size)
{
    __shared__ float sv[128];
    __shared__ int   si[128];
    const int row = blockIdx.x;
    const int tid = threadIdx.x;
    const float best = decf(rb[row]);
    const float thr = best + 0.033f * zn[row] * cmax[0] + 0.1f;

    float bv = 3.4e38f; int bi = 0x7FFFFFFF;
    const float* zp = zf + (size_t)row * 512;
    for (int c = tid; c < 8192; c += 128) {
        float s = sc[(size_t)row * 8192 + c];
        if (s <= thr) {
            const float* cp = cb + (size_t)c * 512;
            float dot = 0.f;
            for (int d = 0; d < 512; d += 4) {
                float4 zv = *(const float4*)(zp + d);
                float4 cv = *(const float4*)(cp + d);
                dot = fmaf(zv.x, cv.x, dot);
                dot = fmaf(zv.y, cv.y, dot);
                dot = fmaf(zv.z, cv.z, dot);
                dot = fmaf(zv.w, cv.w, dot);
            }
            float dd = cn[c] - 2.f * dot;
            if (dd < bv || (dd == bv && c < bi)) { bv = dd; bi = c; }
        }
    }
    sv[tid] = bv; si[tid] = bi;
    __syncthreads();
    for (int s = 64; s > 0; s >>= 1) {
        if (tid < s) {
            float ov = sv[tid + s]; int oi = si[tid + s];
            if (ov < sv[tid] || (ov == sv[tid] && oi < si[tid])) { sv[tid] = ov; si[tid] = oi; }
        }
        __syncthreads();
    }
    if (tid == 0) {
        idx[row] = si[0];
        long o = out_off + row;
        if (o < out_size) out[o] = (float)si[0];
    }
}

// ---------------- zq emit (bf16 hi/lo channels-last) ----------------
__global__ void __launch_bounds__(256) zqemit_k(const float* __restrict__ cb,
                                                const int* __restrict__ idx,
                                                __nv_bfloat16* __restrict__ zqh,
                                                __nv_bfloat16* __restrict__ zql)
{
    const int r0 = blockIdx.x * 32;
    const int tid = threadIdx.x;
    for (int i = tid; i < 32 * 512; i += 256) {
        int x = i >> 9, c = i & 511;
        float v = cb[(size_t)idx[r0 + x] * 512 + c];
        __nv_bfloat16 h = __float2bfloat16(v);
        float r = v - __bfloat162float(h);
        size_t px = (size_t)r0 + x;
        zqh[px * 512 + c] = h;
        zql[px * 512 + c] = __float2bfloat16(r);
    }
}

// ---------------- deconv via WMMA split-bf16 polyphase GEMM (R13) ----------------
template<int NFRAG, int OUTF>
__global__ void __launch_bounds__(256) deconvW_k(
    const __nv_bfloat16* __restrict__ inH, const __nv_bfloat16* __restrict__ inL,
    const __nv_bfloat16* __restrict__ wH,  const __nv_bfloat16* __restrict__ wL,
    const float* __restrict__ bias,
    __nv_bfloat16* __restrict__ outH, __nv_bfloat16* __restrict__ outL,
    float* __restrict__ outF,
    int Cin, int Cout, int Hin, int Win, int ytiles, int xtiles, int nch)
{
    constexpr int NT = NFRAG * 32;
    extern __shared__ char smem[];
    __nv_bfloat16* AsH = (__nv_bfloat16*)smem;
    __nv_bfloat16* AsL = (__nv_bfloat16*)(smem + 18432);
    __nv_bfloat16* BsH = (__nv_bfloat16*)(smem + 36864);
    __nv_bfloat16* BsL = (__nv_bfloat16*)(smem + 36864 + NT * 144);
    float* Cs = (float*)smem;
    const int ldC = NT + 8;

    const int tid = threadIdx.x, wid = tid >> 5;
    const int wm = wid >> 1, wn = wid & 1;

    int b = blockIdx.x;
    const int och = b % nch; b /= nch;
    const int x0  = (b % xtiles) * 32; b /= xtiles;
    const int y0  = (b % ytiles) * 4;  b /= ytiles;
    const int n   = b;
    const int Hout = Hin * 2, Wout = Win * 2;
    const int nkc = Cin >> 6;

    for (int cls = 0; cls < 4; cls++) {
        const int dy = cls >> 1, dx = cls & 1;
        int kys[2], sys[2], nky, kxs[2], sxs[2], nkx;
        if (dy == 0) { kys[0]=1; sys[0]=0; nky=1; }
        else         { kys[0]=2; sys[0]=0; kys[1]=0; sys[1]=1; nky=2; }
        if (dx == 0) { kxs[0]=1; sxs[0]=0; nkx=1; }
        else         { kxs[0]=2; sxs[0]=0; kxs[1]=0; sxs[1]=1; nkx=2; }

        wmma::fragment<wmma::accumulator, 16, 16, 16, float> acc[2][NFRAG];
#pragma unroll
        for (int mf = 0; mf < 2; mf++)
#pragma unroll
            for (int nf = 0; nf < NFRAG; nf++) wmma::fill_fragment(acc[mf][nf], 0.f);

        for (int ti = 0; ti < nky * nkx; ti++) {
            const int ky = kys[ti / nkx], sy = sys[ti / nkx];
            const int kx = kxs[ti % nkx], sx = sxs[ti % nkx];
            const int tap = ky * 3 + kx;
            const __nv_bfloat16* BgH = wH + (size_t)tap * Cout * Cin;
            const __nv_bfloat16* BgL = wL + (size_t)tap * Cout * Cin;
            for (int kc = 0; kc < nkc; kc++) {
                const int ck0 = kc * 64;
                __syncthreads();
                for (int i = tid; i < 2048; i += 256) {
                    int half = i >> 10;
                    int r2 = i & 1023;
                    int row = r2 >> 3, e = r2 & 7;
                    int ii = row >> 5, jj = row & 31;
                    int gy = y0 + ii + sy, gx = x0 + jj + sx;
                    uint4 v = make_uint4(0u, 0u, 0u, 0u);
                    const __nv_bfloat16* Ag = half ? inL : inH;
                    if (gy < Hin && gx < Win)
                        v = *(const uint4*)(Ag + (((size_t)n * Hin + gy) * Win + gx) * Cin + ck0 + e * 8);
                    *(uint4*)(smem + half * 18432 + row * 144 + e * 16) = v;
                }
                for (int i = tid; i < NT * 16; i += 256) {
                    int half = (i >= NT * 8) ? 1 : 0;
                    int r2 = half ? i - NT * 8 : i;
                    int row = r2 >> 3, e = r2 & 7;
                    const __nv_bfloat16* Bg = half ? BgL : BgH;
                    uint4 v = *(const uint4*)(Bg + (size_t)(och * NT + row) * Cin + ck0 + e * 8);
                    *(uint4*)(smem + 36864 + half * (NT * 144) + row * 144 + e * 16) = v;
                }
                __syncthreads();
#pragma unroll
                for (int kf = 0; kf < 4; kf++) {
                    wmma::fragment<wmma::matrix_a, 16, 16, 16, __nv_bfloat16, wmma::row_major> aH0, aH1, aL0, aL1;
                    wmma::load_matrix_sync(aH0, AsH + (wm * 32) * 72 + kf * 16, 72);
                    wmma::load_matrix_sync(aH1, AsH + (wm * 32 + 16) * 72 + kf * 16, 72);
                    wmma::load_matrix_sync(aL0, AsL + (wm * 32) * 72 + kf * 16, 72);
                    wmma::load_matrix_sync(aL1, AsL + (wm * 32 + 16) * 72 + kf * 16, 72);
#pragma unroll
                    for (int nf = 0; nf < NFRAG; nf++) {
                        wmma::fragment<wmma::matrix_b, 16, 16, 16, __nv_bfloat16, wmma::col_major> bH, bL;
                        wmma::load_matrix_sync(bH, BsH + (wn * (NT / 2) + nf * 16) * 72 + kf * 16, 72);
                        wmma::load_matrix_sync(bL, BsL + (wn * (NT / 2) + nf * 16) * 72 + kf * 16, 72);
                        wmma::mma_sync(acc[0][nf], aH0, bH, acc[0][nf]);
                        wmma::mma_sync(acc[1][nf], aH1, bH, acc[1][nf]);
                        wmma::mma_sync(acc[0][nf], aH0, bL, acc[0][nf]);
                        wmma::mma_sync(acc[1][nf], aH1, bL, acc[1][nf]);
                        wmma::mma_sync(acc[0][nf], aL0, bH, acc[0][nf]);
                        wmma::mma_sync(acc[1][nf], aL1, bH, acc[1][nf]);
                    }
                }
            }
        }
        __syncthreads();
#pragma unroll
        for (int mf = 0; mf < 2; mf++)
#pragma unroll
            for (int nf = 0; nf < NFRAG; nf++)
                wmma::store_matrix_sync(Cs + (wm * 32 + mf * 16) * ldC + wn * (NT / 2) + nf * 16,
                                        acc[mf][nf], ldC, wmma::mem_row_major);
        __syncthreads();
        for (int i = tid; i < 128 * NT; i += 256) {
            int m = i / NT, oc = i % NT;
            int ii = m >> 5, jj = m & 31;
            int oy = 2 * (y0 + ii) + dy, ox = 2 * (x0 + jj) + dx;
            int ocg = och * NT + oc;
            float v = Cs[m * ldC + oc] + bias[ocg];
            v = v > 0.f ? v : 0.f;
            if (OUTF) {
                outF[(((size_t)n * Cout + ocg) * Hout + oy) * Wout + ox] = v;
            } else {
                __nv_bfloat16 h = __float2bfloat16(v);
                float r = v - __bfloat162float(h);
                size_t px = ((size_t)n * Hout + oy) * Wout + ox;
                outH[px * Cout + ocg] = h;
                outL[px * Cout + ocg] = __float2bfloat16(r);
            }
        }
        __syncthreads();
    }
}

// ---------------- host launcher ----------------
extern "C" void kernel_launch(void* const* d_in, const int* in_sizes, int n_in,
                              void* d_out, int out_size)
{
    const float* x  = (const float*)d_in[0];
    const float* w1 = (const float*)d_in[1];  const float* b1 = (const float*)d_in[2];
    const float* w2 = (const float*)d_in[3];  const float* b2 = (const float*)d_in[4];
    const float* w3 = (const float*)d_in[5];  const float* b3 = (const float*)d_in[6];
    const float* w4 = (const float*)d_in[7];  const float* b4 = (const float*)d_in[8];
    const float* cb = (const float*)d_in[9];
    const float* d1w = (const float*)d_in[10]; const float* d1b = (const float*)d_in[11];
    const float* d2w = (const float*)d_in[12]; const float* d2b = (const float*)d_in[13];
    const float* d3w = (const float*)d_in[14]; const float* d3b = (const float*)d_in[15];
    const float* wo = (const float*)d_in[16]; const float* bo = (const float*)d_in[17];
    float* out = (float*)d_out;

    float *h1, *h2, *h3, *z, *zf, *g3, *cn, *sc, *zn, *cm;
    unsigned int* rb;
    int* idx;
    __nv_bfloat16 *zfh, *cbh, *zqh, *zql, *g1h, *g1l, *g2h, *g2l;
    __nv_bfloat16 *w1h, *w1l, *w2h, *w2l, *w3h, *w3l;
    cudaGetSymbolAddress((void**)&h1, g_h1);
    cudaGetSymbolAddress((void**)&h2, g_h2);
    cudaGetSymbolAddress((void**)&h3, g_h3);
    cudaGetSymbolAddress((void**)&z,  g_z);
    cudaGetSymbolAddress((void**)&zf, g_zf);
    cudaGetSymbolAddress((void**)&g3, g_g3);
    cudaGetSymbolAddress((void**)&cn, g_cn);
    cudaGetSymbolAddress((void**)&sc, g_sc);
    cudaGetSymbolAddress((void**)&zn, g_zn);
    cudaGetSymbolAddress((void**)&cm, g_cmax);
    cudaGetSymbolAddress((void**)&rb, g_rb);
    cudaGetSymbolAddress((void**)&idx, g_idx);
    cudaGetSymbolAddress((void**)&zfh, g_zfh);
    cudaGetSymbolAddress((void**)&cbh, g_cbh);
    cudaGetSymbolAddress((void**)&zqh, g_zqh);
    cudaGetSymbolAddress((void**)&zql, g_zql);
    cudaGetSymbolAddress((void**)&g1h, g_g1h);
    cudaGetSymbolAddress((void**)&g1l, g_g1l);
    cudaGetSymbolAddress((void**)&g2h, g_g2h);
    cudaGetSymbolAddress((void**)&g2l, g_g2l);
    cudaGetSymbolAddress((void**)&w1h, g_w1h);
    cudaGetSymbolAddress((void**)&w1l, g_w1l);
    cudaGetSymbolAddress((void**)&w2h, g_w2h);
    cudaGetSymbolAddress((void**)&w2l, g_w2l);
    cudaGetSymbolAddress((void**)&w3h, g_w3h);
    cudaGetSymbolAddress((void**)&w3l, g_w3l);

    // independent prep
    cnorm_k<<<1024, 256>>>(cb, cn);
    cmax_k<<<1, 256>>>(cn, cm);
    cbsplit_k<<<(8192 * 512 + 255) / 256, 256>>>(cb, cbh);
    rbinit_k<<<64, 256>>>(rb);
    wprep_k<<<(9 * 512 * 256 + 255) / 256, 256>>>(d1w, w1h, w1l, 512, 256);
    wprep_k<<<(9 * 256 * 128 + 255) / 256, 256>>>(d2w, w2h, w2l, 256, 128);
    wprep_k<<<(9 * 128 *  64 + 255) / 256, 256>>>(d3w, w3h, w3l, 128, 64);

    // Encoder (exact fp32)
    conv8s_k<1, 8, 1><<<dim3( 8, 64, NB), 128>>>(x,  w1, b1, h1,   3,  64, 256, 256, 256, 256);
    conv8s_k<2, 8, 1><<<dim3(16, 16, NB), 128>>>(h1, w2, b2, h2,  64, 128, 256, 256, 128, 128);
    conv8s_k<2, 8, 1><<<dim3(32,  4, NB), 128>>>(h2, w3, b3, h3, 128, 256, 128, 128,  64,  64);
    conv8s_k<2, 8, 0><<<dim3(64,  1, NB), 128>>>(h3, w4, b4, z,  256, 512,  64,  64,  32,  32);

    // Quantize: 1-pass bf16 approx scores + rigorous-threshold exact recheck
    zt_k<<<512, 256>>>(z, zf, zfh, zn);
    cudaFuncSetAttribute(qgemm_k, cudaFuncAttributeMaxDynamicSharedMemorySize, 69632);
    qgemm_k<<<dim3(128, 64), 256, 69632>>>(zfh, cbh, cn, sc, rb);
    qsel_k<<<16384, 128>>>(sc, rb, cn, zf, cb, zn, cm, idx, out,
                           (long)NB * 3 * 256 * 256, (long)out_size);
    zqemit_k<<<512, 256>>>(cb, idx, zqh, zql);

    // Decoder: WMMA split-bf16 polyphase GEMMs
    const int sm4 = 36864 + 2 * 128 * 144;
    const int sm2 = 36864 + 2 *  64 * 144;
    cudaFuncSetAttribute((const void*)deconvW_k<4, 0>, cudaFuncAttributeMaxDynamicSharedMemorySize, sm4);
    cudaFuncSetAttribute((const void*)deconvW_k<2, 1>, cudaFuncAttributeMaxDynamicSharedMemorySize, sm2);

    deconvW_k<4, 0><<<NB * 8 * 1 * 2, 256, sm4>>>(zqh, zql, w1h, w1l, d1b,
                                                  g1h, g1l, nullptr,
                                                  512, 256, 32, 32, 8, 1, 2);
    deconvW_k<4, 0><<<NB * 16 * 2 * 1, 256, sm4>>>(g1h, g1l, w2h, w2l, d2b,
                                                   g2h, g2l, nullptr,
                                                   256, 128, 64, 64, 16, 2, 1);
    deconvW_k<2, 1><<<NB * 32 * 4 * 1, 256, sm2>>>(g2h, g2l, w3h, w3l, d3b,
                                                   nullptr, nullptr, g3,
                                                   128, 64, 128, 128, 32, 4, 1);

    // Final sigmoid conv (scalar)
    conv8s_k<1, 3, 2><<<dim3(1, 64, NB), 128>>>(g3, wo, bo, out, 64, 3, 256, 256, 256, 256);
}